// round 3
// baseline (speedup 1.0000x reference)
#include <cuda_runtime.h>
#include <math.h>

#define BB 4
#define NN 2048
#define DD 1024
#define DK 64
#define BN (BB * NN)
#define NSTEPS 4
#define KCHUNKS 4

// ---------------- device scratch ----------------
__device__ float  g_compat[(size_t)BN * NN];          // 64 MB
__device__ float  g_part[(size_t)KCHUNKS * BN * 128]; // split-k partials
__device__ float  g_fgelu[BN * 64];                   // gelu(fpre + b1)
__device__ float  g_V[BN * DK];
__device__ float  g_Q[BN * DK];
__device__ float  g_K[BN * DK];
__device__ float  g_charge0[BN];
__device__ float4 g_C4[BN];                           // charge snapshots
__device__ float  g_received[BN];
__device__ float  g_rowinv[BN];
__device__ float  g_attV[BN * DK];

__device__ __forceinline__ float sigmoidf_(float x) { return 1.0f / (1.0f + __expf(-x)); }

// ---------------- init ----------------
__global__ void init_kernel() {
    int idx = blockIdx.x * blockDim.x + threadIdx.x;
    if (idx < BN * DK) g_attV[idx] = 0.0f;
    if (idx < BN) { g_received[idx] = 0.0f; g_C4[idx] = make_float4(0.f, 0.f, 0.f, 0.f); }
}

// ---------------- GEMM1 split-k: hidden[BN,1024] @ [W1;Wv]^T, 128x128 tile, 8x8 regs ----------------
__global__ __launch_bounds__(256) void gemm1_kernel(const float* __restrict__ hidden,
                                                    const float* __restrict__ W1,
                                                    const float* __restrict__ Wv) {
    __shared__ float An[128][32];    // natural [m][k]
    __shared__ float Bt[32][132];    // transposed [k][n]
    const int tid = threadIdx.x;
    const int m0 = blockIdx.x * 128;
    const int kc = blockIdx.y;
    const int tr = tid >> 4, tc = tid & 15;
    float acc[8][8];
#pragma unroll
    for (int i = 0; i < 8; i++)
#pragma unroll
        for (int j = 0; j < 8; j++) acc[i][j] = 0.0f;

    const int kbeg = kc * (DD / KCHUNKS);
    for (int k0 = kbeg; k0 < kbeg + DD / KCHUNKS; k0 += 32) {
#pragma unroll
        for (int it = 0; it < 4; it++) {
            int q = tid + it * 256;
            int m = q >> 3;
            int kg = (q & 7) << 2;
            float4 v = *(const float4*)(hidden + (size_t)(m0 + m) * DD + k0 + kg);
            *(float4*)&An[m][kg] = v;
            const float* wr = (m < 64) ? (W1 + (size_t)m * DD) : (Wv + (size_t)(m - 64) * DD);
            float4 w = *(const float4*)(wr + k0 + kg);
            Bt[kg + 0][m] = w.x; Bt[kg + 1][m] = w.y;
            Bt[kg + 2][m] = w.z; Bt[kg + 3][m] = w.w;
        }
        __syncthreads();
#pragma unroll
        for (int k = 0; k < 32; k++) {
            float ra[8], rb[8];
#pragma unroll
            for (int i = 0; i < 4; i++) {
                ra[i]     = An[tr * 4 + i][k];
                ra[4 + i] = An[64 + tr * 4 + i][k];
            }
            float4 b0 = *(float4*)&Bt[k][tc * 4];
            float4 b1 = *(float4*)&Bt[k][tc * 4 + 64];
            rb[0] = b0.x; rb[1] = b0.y; rb[2] = b0.z; rb[3] = b0.w;
            rb[4] = b1.x; rb[5] = b1.y; rb[6] = b1.z; rb[7] = b1.w;
#pragma unroll
            for (int i = 0; i < 8; i++)
#pragma unroll
                for (int j = 0; j < 8; j++) acc[i][j] += ra[i] * rb[j];
        }
        __syncthreads();
    }
    float* pbase = g_part + (size_t)kc * BN * 128;
#pragma unroll
    for (int i = 0; i < 8; i++) {
        int r = m0 + tr * 4 + (i & 3) + (i >> 2) * 64;
        *(float4*)(pbase + (size_t)r * 128 + tc * 4)      = make_float4(acc[i][0], acc[i][1], acc[i][2], acc[i][3]);
        *(float4*)(pbase + (size_t)r * 128 + tc * 4 + 64) = make_float4(acc[i][4], acc[i][5], acc[i][6], acc[i][7]);
    }
}

// ---------------- reduce split-k + fused gelu ----------------
__global__ __launch_bounds__(256) void reduce_kernel(const float* __restrict__ b1) {
    int idx = blockIdx.x * blockDim.x + threadIdx.x;
    if (idx >= BN * 128) return;
    const size_t off = (size_t)BN * 128;
    float s = g_part[idx] + g_part[idx + off] + g_part[idx + 2 * off] + g_part[idx + 3 * off];
    int row = idx >> 7, c = idx & 127;
    if (c < 64) {
        float x = s + b1[c];
        g_fgelu[row * 64 + c] = 0.5f * x * (1.0f + erff(x * 0.7071067811865475f));
    } else {
        g_V[row * DK + (c - 64)] = s;
    }
}

// ---------------- feature net: sigmoid MLP -> Q,K,charge0 (16 rows/block) ----------------
__global__ __launch_bounds__(256) void feat_kernel(const float* __restrict__ W2,
                                                   const float* __restrict__ b2,
                                                   const float* __restrict__ Wq,
                                                   const float* __restrict__ Wk,
                                                   const float* __restrict__ Wc,
                                                   const float* __restrict__ bc) {
    __shared__ float W2s[28][65];
    __shared__ float Wqs[64][29];
    __shared__ float Wks[64][29];
    __shared__ float fsS[16][65];
    __shared__ float featS[16][29];
    __shared__ float b2s[28], WcS[28];
    const int tid = threadIdx.x;
    const int r0 = blockIdx.x * 16;

    for (int idx = tid; idx < 28 * 64; idx += 256) W2s[idx >> 6][idx & 63] = W2[idx];
    for (int idx = tid; idx < 64 * 28; idx += 256) {
        int d = idx / 28, k = idx - d * 28;
        Wqs[d][k] = Wq[idx];
        Wks[d][k] = Wk[idx];
    }
    if (tid < 28) { b2s[tid] = b2[tid]; WcS[tid] = Wc[tid]; }
    for (int idx = tid; idx < 16 * 64; idx += 256) {
        int r = idx >> 6, c = idx & 63;
        fsS[r][c] = g_fgelu[(r0 + r) * 64 + c];
    }
    __syncthreads();

    const int r = tid >> 4, t16 = tid & 15;
    for (int o = t16; o < 28; o += 16) {
        float s = b2s[o];
#pragma unroll
        for (int k = 0; k < 64; k++) s += W2s[o][k] * fsS[r][k];
        featS[r][o] = sigmoidf_(s);
    }
    __syncthreads();

#pragma unroll
    for (int dd = 0; dd < 4; dd++) {
        int d = t16 + dd * 16;
        float q = 0.f, kv = 0.f;
#pragma unroll
        for (int k = 0; k < 28; k++) {
            float f = featS[r][k];
            q  += Wqs[d][k] * f;
            kv += Wks[d][k] * f;
        }
        g_Q[(r0 + r) * DK + d] = q;
        g_K[(r0 + r) * DK + d] = kv;
    }
    if (tid < 16) {
        float s = bc[0];
#pragma unroll
        for (int k = 0; k < 28; k++) s += WcS[k] * featS[tid][k];
        g_charge0[r0 + tid] = sigmoidf_(s);
    }
}

// ---------------- compat = Q K^T / 8, 128x128 causal tiles, 8x8 regs, dynamic smem ----------------
__global__ __launch_bounds__(256) void compat_kernel() {
    extern __shared__ float dsm1[];
    float (*Qn)[64]  = (float(*)[64])dsm1;             // [128][64] natural
    float (*Kt)[132] = (float(*)[132])(dsm1 + 128 * 64); // [64][132] transposed
    const int b = blockIdx.y;
    int t = blockIdx.x;
    int i = 0;
    while ((i + 1) * (i + 2) / 2 <= t) i++;
    int j = t - i * (i + 1) / 2;
    const int tid = threadIdx.x;
    const int tr = tid >> 4, tc = tid & 15;

#pragma unroll
    for (int it = 0; it < 8; it++) {
        int q = tid + it * 256;
        int m = q >> 4;
        int kg = (q & 15) << 2;
        float4 v = *(const float4*)(g_Q + (size_t)(b * NN + i * 128 + m) * DK + kg);
        *(float4*)&Qn[m][kg] = v;
        float4 w = *(const float4*)(g_K + (size_t)(b * NN + j * 128 + m) * DK + kg);
        Kt[kg + 0][m] = w.x; Kt[kg + 1][m] = w.y;
        Kt[kg + 2][m] = w.z; Kt[kg + 3][m] = w.w;
    }
    __syncthreads();

    float acc[8][8];
#pragma unroll
    for (int x = 0; x < 8; x++)
#pragma unroll
        for (int y = 0; y < 8; y++) acc[x][y] = 0.0f;
#pragma unroll
    for (int k = 0; k < 64; k++) {
        float ra[8], rb[8];
#pragma unroll
        for (int x = 0; x < 4; x++) {
            ra[x]     = Qn[tr * 4 + x][k];
            ra[4 + x] = Qn[64 + tr * 4 + x][k];
        }
        float4 b0 = *(float4*)&Kt[k][tc * 4];
        float4 b1 = *(float4*)&Kt[k][tc * 4 + 64];
        rb[0] = b0.x; rb[1] = b0.y; rb[2] = b0.z; rb[3] = b0.w;
        rb[4] = b1.x; rb[5] = b1.y; rb[6] = b1.z; rb[7] = b1.w;
#pragma unroll
        for (int x = 0; x < 8; x++)
#pragma unroll
            for (int y = 0; y < 8; y++) acc[x][y] += ra[x] * rb[y];
    }
#pragma unroll
    for (int x = 0; x < 8; x++) {
        int n = i * 128 + tr * 4 + (x & 3) + (x >> 2) * 64;
        float* dst = g_compat + (size_t)(b * NN + n) * NN + j * 128;
        *(float4*)(dst + tc * 4)      = make_float4(acc[x][0] * 0.125f, acc[x][1] * 0.125f, acc[x][2] * 0.125f, acc[x][3] * 0.125f);
        *(float4*)(dst + tc * 4 + 64) = make_float4(acc[x][4] * 0.125f, acc[x][5] * 0.125f, acc[x][6] * 0.125f, acc[x][7] * 0.125f);
    }
}

// ---------------- rowsum (vectorized) ----------------
__global__ __launch_bounds__(256) void rowsum_kernel(const float* __restrict__ step_p) {
    const int bn = blockIdx.x;
    const int b = bn >> 11;
    const int n = bn & (NN - 1);
    const int L = n + 1;
    const int tid = threadIdx.x;
    const float step = *step_p;
    float4 cn = g_C4[bn];
    cn.x *= step; cn.y *= step; cn.z *= step; cn.w *= step;
    const float4* crow4 = (const float4*)(g_compat + (size_t)bn * NN);
    const float4* cb = g_C4 + b * NN;

    float s = 0.0f;
    const int nv4 = L >> 2;
    for (int m4 = tid; m4 < nv4; m4 += 256) {
        float4 cv = crow4[m4];
        float4 c0 = cb[m4 * 4 + 0], c1 = cb[m4 * 4 + 1], c2 = cb[m4 * 4 + 2], c3 = cb[m4 * 4 + 3];
        s += __expf(cv.x * (1.0f + cn.x * c0.x + cn.y * c0.y + cn.z * c0.z + cn.w * c0.w));
        s += __expf(cv.y * (1.0f + cn.x * c1.x + cn.y * c1.y + cn.z * c1.z + cn.w * c1.w));
        s += __expf(cv.z * (1.0f + cn.x * c2.x + cn.y * c2.y + cn.z * c2.z + cn.w * c2.w));
        s += __expf(cv.w * (1.0f + cn.x * c3.x + cn.y * c3.y + cn.z * c3.z + cn.w * c3.w));
    }
    {
        int m = (nv4 << 2) + tid;
        if (m < L) {
            float4 cm = cb[m];
            float coef = 1.0f + cn.x * cm.x + cn.y * cm.y + cn.z * cm.z + cn.w * cm.w;
            s += __expf(g_compat[(size_t)bn * NN + m] * coef);
        }
    }
#pragma unroll
    for (int o = 16; o > 0; o >>= 1) s += __shfl_xor_sync(0xffffffffu, s, o);
    __shared__ float red[8];
    if ((tid & 31) == 0) red[tid >> 5] = s;
    __syncthreads();
    if (tid == 0) {
        float t = red[0] + red[1] + red[2] + red[3] + red[4] + red[5] + red[6] + red[7];
        g_rowinv[bn] = 1.0f / t;
    }
}

// ---------------- colsum ----------------
__global__ __launch_bounds__(256) void colsum_kernel(const float* __restrict__ step_p) {
    const int i = blockIdx.x;
    const int b = blockIdx.y;
    const int chunk = blockIdx.z;
    if (chunk > i) return;
    __shared__ float4 cnS[64];
    __shared__ float4 cmS[64];
    __shared__ float rinvS[64];
    __shared__ float colS[4][64];
    const int tid = threadIdx.x;
    const float step = *step_p;
    if (tid < 64) {
        int gn = b * NN + i * 64 + tid;
        float4 c = g_C4[gn];
        c.x *= step; c.y *= step; c.z *= step; c.w *= step;
        cnS[tid] = c;
        rinvS[tid] = g_rowinv[gn];
    }
    const int c = tid & 63;
    const int rg = tid >> 6;
    for (int j = chunk; j <= i; j += 8) {
        __syncthreads();
        if (tid < 64) cmS[tid] = g_C4[b * NN + j * 64 + tid];
        __syncthreads();
        float4 cm = cmS[c];
        float colsum = 0.0f;
        const float* cbase = g_compat + (size_t)(b * NN + i * 64) * NN + j * 64 + c;
        if (j < i) {
#pragma unroll 4
            for (int rr = 0; rr < 16; rr++) {
                int r = rg + 4 * rr;
                float4 cn = cnS[r];
                float coef = 1.0f + cn.x * cm.x + cn.y * cm.y + cn.z * cm.z + cn.w * cm.w;
                colsum += __expf(cbase[(size_t)r * NN] * coef) * rinvS[r];
            }
        } else {
            for (int rr = 0; rr < 16; rr++) {
                int r = rg + 4 * rr;
                if (c <= r) {
                    float4 cn = cnS[r];
                    float coef = 1.0f + cn.x * cm.x + cn.y * cm.y + cn.z * cm.z + cn.w * cm.w;
                    colsum += __expf(cbase[(size_t)r * NN] * coef) * rinvS[r];
                }
            }
        }
        colS[rg][c] = colsum;
        __syncthreads();
        if (tid < 64) {
            float v = colS[0][tid] + colS[1][tid] + colS[2][tid] + colS[3][tid];
            atomicAdd(g_received + b * NN + j * 64 + tid, v);
        }
    }
}

// ---------------- charge update ----------------
__global__ void charge_kernel(int p, const float* __restrict__ decay_p) {
    int idx = blockIdx.x * blockDim.x + threadIdx.x;
    if (idx >= BN) return;
    float decay = *decay_p;
    float r = g_received[idx];
    float* c4 = (float*)g_C4;
    float cprev = (p == 0) ? g_charge0[idx] : c4[idx * 4 + (p - 1)];
    c4[idx * 4 + p] = cprev * (1.0f - decay * sigmoidf_(r - 1.0f));
    g_received[idx] = 0.0f;
}

// ---------------- attn@V: 128-row tiles, m-tiles of 64, 8x4 regs, dynamic smem ----------------
__global__ __launch_bounds__(256) void attnv_kernel(const float* __restrict__ step_p) {
    extern __shared__ float dsm2[];
    float (*attnS)[64] = (float(*)[64])dsm2;            // [128][64] natural [r][m]
    float (*Vs)[68]    = (float(*)[68])(dsm2 + 128 * 64); // [64][68]
    __shared__ float4 cnS[128];
    __shared__ float4 cmS[64];
    __shared__ float rinvS[128];
    const int i = blockIdx.x;
    const int b = blockIdx.y;
    const int chunk = blockIdx.z;
    const int jmax = 2 * i + 1;
    if (chunk > jmax) return;
    const int tid = threadIdx.x;
    const int tr = tid >> 4, tc = tid & 15;
    const float step = *step_p;
    if (tid < 128) {
        int gn = b * NN + i * 128 + tid;
        float4 cc = g_C4[gn];
        cc.x *= step; cc.y *= step; cc.z *= step; cc.w *= step;
        cnS[tid] = cc;
        rinvS[tid] = g_rowinv[gn];
    }
    float acc[8][4];
#pragma unroll
    for (int x = 0; x < 8; x++)
#pragma unroll
        for (int y = 0; y < 4; y++) acc[x][y] = 0.0f;

    for (int j = chunk; j <= jmax; j += 4) {
        const int m0 = j * 64;
        __syncthreads();
        if (tid < 64) cmS[tid] = g_C4[b * NN + m0 + tid];
#pragma unroll
        for (int it = 0; it < 4; it++) {
            int q = tid + it * 256;
            int m = q >> 4;
            int d4 = (q & 15) << 2;
            float4 v = *(const float4*)(g_V + (size_t)(b * NN + m0 + m) * DK + d4);
            *(float4*)&Vs[m][d4] = v;
        }
        __syncthreads();
#pragma unroll
        for (int it = 0; it < 32; it++) {
            int q = tid + it * 256;
            int m = q & 63, r = q >> 6;
            int n = i * 128 + r, mg = m0 + m;
            float v = 0.0f;
            if (mg <= n) {
                float4 cn = cnS[r], cm = cmS[m];
                float coef = 1.0f + cn.x * cm.x + cn.y * cm.y + cn.z * cm.z + cn.w * cm.w;
                v = __expf(g_compat[(size_t)(b * NN + n) * NN + mg] * coef) * rinvS[r];
            }
            attnS[r][m] = v;
        }
        __syncthreads();
#pragma unroll 4
        for (int k = 0; k < 64; k++) {
            float ra[8];
#pragma unroll
            for (int x = 0; x < 4; x++) {
                ra[x]     = attnS[tr * 4 + x][k];
                ra[4 + x] = attnS[64 + tr * 4 + x][k];
            }
            float4 b0 = *(float4*)&Vs[k][tc * 4];
            float rb[4] = {b0.x, b0.y, b0.z, b0.w};
#pragma unroll
            for (int x = 0; x < 8; x++)
#pragma unroll
                for (int y = 0; y < 4; y++) acc[x][y] += ra[x] * rb[y];
        }
    }
#pragma unroll
    for (int x = 0; x < 8; x++) {
        int r = i * 128 + tr * 4 + (x & 3) + (x >> 2) * 64;
        float* dst = g_attV + (size_t)(b * NN + r) * DK + tc * 4;
#pragma unroll
        for (int y = 0; y < 4; y++) atomicAdd(dst + y, acc[x][y]);
    }
}

// ---------------- out = 0.1 * attV @ Wo^T, 128x128 tile, dynamic smem ----------------
__global__ __launch_bounds__(256) void outgemm_kernel(const float* __restrict__ Wo,
                                                      float* __restrict__ out) {
    extern __shared__ float dsm3[];
    float (*An)[64]  = (float(*)[64])dsm3;               // [128][64] natural attV tile
    float (*Bt)[132] = (float(*)[132])(dsm3 + 128 * 64); // [64][132] Wo transposed
    const int m0 = blockIdx.x * 128;
    const int n0 = blockIdx.y * 128;
    const int tid = threadIdx.x;
    const int tr = tid >> 4, tc = tid & 15;
#pragma unroll
    for (int it = 0; it < 8; it++) {
        int q = tid + it * 256;
        int m = q >> 4;
        int kg = (q & 15) << 2;
        float4 v = *(const float4*)(g_attV + (size_t)(m0 + m) * DK + kg);
        *(float4*)&An[m][kg] = v;
        float4 w = *(const float4*)(Wo + (size_t)(n0 + m) * DK + kg);
        Bt[kg + 0][m] = w.x; Bt[kg + 1][m] = w.y;
        Bt[kg + 2][m] = w.z; Bt[kg + 3][m] = w.w;
    }
    __syncthreads();
    float acc[8][8];
#pragma unroll
    for (int x = 0; x < 8; x++)
#pragma unroll
        for (int y = 0; y < 8; y++) acc[x][y] = 0.0f;
#pragma unroll
    for (int k = 0; k < 64; k++) {
        float ra[8], rb[8];
#pragma unroll
        for (int x = 0; x < 4; x++) {
            ra[x]     = An[tr * 4 + x][k];
            ra[4 + x] = An[64 + tr * 4 + x][k];
        }
        float4 b0 = *(float4*)&Bt[k][tc * 4];
        float4 b1 = *(float4*)&Bt[k][tc * 4 + 64];
        rb[0] = b0.x; rb[1] = b0.y; rb[2] = b0.z; rb[3] = b0.w;
        rb[4] = b1.x; rb[5] = b1.y; rb[6] = b1.z; rb[7] = b1.w;
#pragma unroll
        for (int x = 0; x < 8; x++)
#pragma unroll
            for (int y = 0; y < 8; y++) acc[x][y] += ra[x] * rb[y];
    }
#pragma unroll
    for (int x = 0; x < 8; x++) {
        size_t base = (size_t)(m0 + tr * 4 + (x & 3) + (x >> 2) * 64) * DD + n0;
        *(float4*)(out + base + tc * 4)      = make_float4(acc[x][0] * 0.1f, acc[x][1] * 0.1f, acc[x][2] * 0.1f, acc[x][3] * 0.1f);
        *(float4*)(out + base + tc * 4 + 64) = make_float4(acc[x][4] * 0.1f, acc[x][5] * 0.1f, acc[x][6] * 0.1f, acc[x][7] * 0.1f);
    }
}

// ---------------- launch ----------------
extern "C" void kernel_launch(void* const* d_in, const int* in_sizes, int n_in,
                              void* d_out, int out_size) {
    const float* hidden  = (const float*)d_in[0];
    const float* W1      = (const float*)d_in[1];
    const float* b1      = (const float*)d_in[2];
    const float* W2      = (const float*)d_in[3];
    const float* b2      = (const float*)d_in[4];
    const float* Wq      = (const float*)d_in[5];
    const float* Wk      = (const float*)d_in[6];
    const float* Wc      = (const float*)d_in[7];
    const float* bc      = (const float*)d_in[8];
    const float* Wv      = (const float*)d_in[9];
    const float* Wo      = (const float*)d_in[10];
    const float* step_p  = (const float*)d_in[11];
    const float* decay_p = (const float*)d_in[12];
    float* out = (float*)d_out;

    const int SM_BIG   = (128 * 64 + 64 * 132) * 4;   // 66560
    const int SM_ATTNV = (128 * 64 + 64 * 68) * 4;    // 50176
    cudaFuncSetAttribute(compat_kernel,  cudaFuncAttributeMaxDynamicSharedMemorySize, SM_BIG);
    cudaFuncSetAttribute(outgemm_kernel, cudaFuncAttributeMaxDynamicSharedMemorySize, SM_BIG);
    cudaFuncSetAttribute(attnv_kernel,   cudaFuncAttributeMaxDynamicSharedMemorySize, SM_ATTNV);

    init_kernel<<<2048, 256>>>();
    gemm1_kernel<<<dim3(64, KCHUNKS), 256>>>(hidden, W1, Wv);
    reduce_kernel<<<4096, 256>>>(b1);
    feat_kernel<<<BN / 16, 256>>>(W2, b2, Wq, Wk, Wc, bc);
    compat_kernel<<<dim3(136, BB), 256, SM_BIG>>>();
    for (int p = 0; p < NSTEPS; p++) {
        rowsum_kernel<<<BN, 256>>>(step_p);
        colsum_kernel<<<dim3(NN / 64, BB, 8), 256>>>(step_p);
        charge_kernel<<<BN / 256, 256>>>(p, decay_p);
    }
    rowsum_kernel<<<BN, 256>>>(step_p);
    attnv_kernel<<<dim3(NN / 128, BB, 4), 256, SM_ATTNV>>>(step_p);
    outgemm_kernel<<<dim3(BN / 128, DD / 128), 256, SM_BIG>>>(Wo, out);
}

// round 5
// speedup vs baseline: 1.0017x; 1.0017x over previous
#include <cuda_runtime.h>
#include <math.h>

#define BB 4
#define NN 2048
#define DD 1024
#define DK 64
#define BN (BB * NN)
#define NSTEPS 4
#define KCHUNKS 4

// compat is stored pre-scaled by 0.125 * log2(e) so every softmax exp is a bare EX2
#define CSCALE 0.18033688011113063f

typedef unsigned long long u64;

// ---------------- f32x2 packed-FMA helpers ----------------
__device__ __forceinline__ void fma2_(u64& d, u64 a, u64 b) {
    asm("fma.rn.f32x2 %0, %1, %2, %0;" : "+l"(d) : "l"(a), "l"(b));
}
__device__ __forceinline__ u64 dup2_(float x) {
    u64 r; asm("mov.b64 %0, {%1, %1};" : "=l"(r) : "f"(x)); return r;
}
__device__ __forceinline__ u64 ld2_(const float* p) { return *(const u64*)p; }
__device__ __forceinline__ float2 unp2_(u64 v) {
    float2 f; asm("mov.b64 {%0, %1}, %2;" : "=f"(f.x), "=f"(f.y) : "l"(v)); return f;
}
__device__ __forceinline__ float ex2_(float x) {
    float y; asm("ex2.approx.ftz.f32 %0, %1;" : "=f"(y) : "f"(x)); return y;
}
__device__ __forceinline__ float sigmoidf_(float x) { return 1.0f / (1.0f + __expf(-x)); }

// ---------------- device scratch ----------------
__device__ float  g_compat[(size_t)BN * NN];          // 64 MB (pre-scaled by CSCALE/0.125 trick)
__device__ float  g_part[(size_t)KCHUNKS * BN * 128];
__device__ float  g_fgelu[BN * 64];
__device__ float  g_V[BN * DK];
__device__ float  g_Q[BN * DK];
__device__ float  g_K[BN * DK];
__device__ float  g_charge0[BN];
__device__ float4 g_C4[BN];
__device__ float  g_received[BN];
__device__ float  g_rowinv[BN];
__device__ float  g_attV[BN * DK];

// ---------------- init ----------------
__global__ void init_kernel() {
    int idx = blockIdx.x * blockDim.x + threadIdx.x;
    if (idx < BN * DK) g_attV[idx] = 0.0f;
    if (idx < BN) { g_received[idx] = 0.0f; g_C4[idx] = make_float4(0.f, 0.f, 0.f, 0.f); }
}

// ---------------- GEMM1 split-k: hidden[BN,1024] @ [W1;Wv]^T -> partials (64x128 tile) ----------------
__global__ __launch_bounds__(256) void gemm1_kernel(const float* __restrict__ hidden,
                                                    const float* __restrict__ W1,
                                                    const float* __restrict__ Wv) {
    __shared__ __align__(16) float Ash[32][66];   // [k][m]
    __shared__ float Bsh[32][128];                // [k][n]
    const int tid = threadIdx.x;
    const int m0 = blockIdx.x * 64;
    const int kc = blockIdx.y;
    const int rg = tid >> 5;
    const int cg = tid & 31;
    u64 accp[4][4];
#pragma unroll
    for (int i = 0; i < 4; i++)
#pragma unroll
        for (int j = 0; j < 4; j++) accp[i][j] = 0ull;

    const int bj = tid & 127;
    const int bks = tid >> 7;
    const float* wbase = (bj < 64) ? (W1 + (size_t)bj * DD) : (Wv + (size_t)(bj - 64) * DD);

    const int kbeg = kc * (DD / KCHUNKS);
    for (int k0 = kbeg; k0 < kbeg + DD / KCHUNKS; k0 += 32) {
#pragma unroll
        for (int it = 0; it < 2; it++) {
            int q = tid + it * 256;
            int r = q >> 3;
            int kk = (q & 7) << 2;
            float4 v = *(const float4*)(hidden + (size_t)(m0 + r) * DD + k0 + kk);
            Ash[kk + 0][r] = v.x; Ash[kk + 1][r] = v.y;
            Ash[kk + 2][r] = v.z; Ash[kk + 3][r] = v.w;
        }
#pragma unroll
        for (int it = 0; it < 4; it++) {
            int kk = (bks + it * 2) << 2;
            float4 w = *(const float4*)(wbase + k0 + kk);
            Bsh[kk + 0][bj] = w.x; Bsh[kk + 1][bj] = w.y;
            Bsh[kk + 2][bj] = w.z; Bsh[kk + 3][bj] = w.w;
        }
        __syncthreads();
#pragma unroll
        for (int k = 0; k < 32; k++) {
            u64 rap[4], rbd[4];
#pragma unroll
            for (int i = 0; i < 4; i++) rap[i] = ld2_(&Ash[k][rg * 8 + 2 * i]);
#pragma unroll
            for (int j = 0; j < 4; j++) rbd[j] = dup2_(Bsh[k][cg + 32 * j]);
#pragma unroll
            for (int i = 0; i < 4; i++)
#pragma unroll
                for (int j = 0; j < 4; j++) fma2_(accp[i][j], rap[i], rbd[j]);
        }
        __syncthreads();
    }
    float* pbase = g_part + (size_t)kc * BN * 128;
#pragma unroll
    for (int i = 0; i < 4; i++) {
        int r0 = m0 + rg * 8 + 2 * i;
#pragma unroll
        for (int j = 0; j < 4; j++) {
            float2 f = unp2_(accp[i][j]);
            pbase[(size_t)r0 * 128 + cg + 32 * j] = f.x;
            pbase[(size_t)(r0 + 1) * 128 + cg + 32 * j] = f.y;
        }
    }
}

// ---------------- reduce split-k + fused gelu ----------------
__global__ __launch_bounds__(256) void reduce_kernel(const float* __restrict__ b1) {
    int idx = blockIdx.x * blockDim.x + threadIdx.x;
    if (idx >= BN * 128) return;
    const size_t off = (size_t)BN * 128;
    float s = g_part[idx] + g_part[idx + off] + g_part[idx + 2 * off] + g_part[idx + 3 * off];
    int row = idx >> 7, c = idx & 127;
    if (c < 64) {
        float x = s + b1[c];
        g_fgelu[row * 64 + c] = 0.5f * x * (1.0f + erff(x * 0.7071067811865475f));
    } else {
        g_V[row * DK + (c - 64)] = s;
    }
}

// ---------------- feature net: warp-per-row (8 rows/block) ----------------
__global__ __launch_bounds__(256) void feat_kernel(const float* __restrict__ W2,
                                                   const float* __restrict__ b2,
                                                   const float* __restrict__ Wq,
                                                   const float* __restrict__ Wk,
                                                   const float* __restrict__ Wc,
                                                   const float* __restrict__ bc) {
    __shared__ float W2s[28][65];
    __shared__ float Wqs[64][29];
    __shared__ float Wks[64][29];
    __shared__ float fsS[8][66];
    __shared__ float featS[8][29];
    __shared__ float b2s[28], WcS[28];
    const int tid = threadIdx.x;
    const int w = tid >> 5, lane = tid & 31;
    const int row = blockIdx.x * 8 + w;

    for (int idx = tid; idx < 28 * 64; idx += 256) W2s[idx >> 6][idx & 63] = W2[idx];
    for (int idx = tid; idx < 64 * 28; idx += 256) {
        int d = idx / 28, k = idx - d * 28;
        Wqs[d][k] = Wq[idx];
        Wks[d][k] = Wk[idx];
    }
    if (tid < 28) { b2s[tid] = b2[tid]; WcS[tid] = Wc[tid]; }
    fsS[w][lane]      = g_fgelu[row * 64 + lane];
    fsS[w][lane + 32] = g_fgelu[row * 64 + lane + 32];
    __syncthreads();

    if (lane < 28) {
        float s = b2s[lane];
#pragma unroll
        for (int k = 0; k < 64; k++) s += W2s[lane][k] * fsS[w][k];
        featS[w][lane] = sigmoidf_(s);
    }
    __syncwarp();

    {
        float q0 = 0.f, k0 = 0.f, q1 = 0.f, k1 = 0.f;
        int d0 = lane, d1 = lane + 32;
#pragma unroll
        for (int k = 0; k < 28; k++) {
            float f = featS[w][k];
            q0 += Wqs[d0][k] * f; k0 += Wks[d0][k] * f;
            q1 += Wqs[d1][k] * f; k1 += Wks[d1][k] * f;
        }
        g_Q[row * DK + d0] = q0; g_K[row * DK + d0] = k0;
        g_Q[row * DK + d1] = q1; g_K[row * DK + d1] = k1;
    }
    if (lane == 0) {
        float s = bc[0];
#pragma unroll
        for (int k = 0; k < 28; k++) s += WcS[k] * featS[w][k];
        g_charge0[row] = sigmoidf_(s);
    }
}

// ---------------- compat = Q K^T * CSCALE, 64x64 causal tiles, f32x2 ----------------
__global__ __launch_bounds__(256) void compat_kernel() {
    const int b = blockIdx.y;
    int t = blockIdx.x;
    int i = 0;
    while ((i + 1) * (i + 2) / 2 <= t) i++;
    int j = t - i * (i + 1) / 2;

    __shared__ __align__(16) float Qsh[64][66];   // [k][r]
    __shared__ float Ksh[64][64];                 // [k][c]
    const int tid = threadIdx.x;
    {
        int r = tid >> 4;
        int kk = (tid & 15) << 2;
#pragma unroll
        for (int it = 0; it < 4; it++) {
            int rr = r + it * 16;
            float4 v = *(const float4*)(g_Q + (size_t)(b * NN + i * 64 + rr) * DK + kk);
            Qsh[kk + 0][rr] = v.x; Qsh[kk + 1][rr] = v.y;
            Qsh[kk + 2][rr] = v.z; Qsh[kk + 3][rr] = v.w;
        }
        int jc = tid & 63;
        int ks0 = tid >> 6;
        const float* kb = g_K + (size_t)(b * NN + j * 64 + jc) * DK;
#pragma unroll
        for (int it = 0; it < 4; it++) {
            int k4 = (ks0 + it * 4) << 2;
            float4 v = *(const float4*)(kb + k4);
            Ksh[k4 + 0][jc] = v.x; Ksh[k4 + 1][jc] = v.y;
            Ksh[k4 + 2][jc] = v.z; Ksh[k4 + 3][jc] = v.w;
        }
    }
    __syncthreads();
    const int tr = tid >> 4, tc = tid & 15;
    u64 accp[2][4];
#pragma unroll
    for (int p = 0; p < 2; p++)
#pragma unroll
        for (int y = 0; y < 4; y++) accp[p][y] = 0ull;
#pragma unroll
    for (int k = 0; k < 64; k++) {
        u64 rap[2], rbd[4];
        rap[0] = ld2_(&Qsh[k][tr * 4]);
        rap[1] = ld2_(&Qsh[k][tr * 4 + 2]);
#pragma unroll
        for (int y = 0; y < 4; y++) rbd[y] = dup2_(Ksh[k][tc + 16 * y]);
#pragma unroll
        for (int p = 0; p < 2; p++)
#pragma unroll
            for (int y = 0; y < 4; y++) fma2_(accp[p][y], rap[p], rbd[y]);
    }
#pragma unroll
    for (int p = 0; p < 2; p++) {
        int n = i * 64 + tr * 4 + 2 * p;
        float* d0 = g_compat + (size_t)(b * NN + n) * NN + j * 64;
        float* d1 = d0 + NN;
#pragma unroll
        for (int y = 0; y < 4; y++) {
            float2 f = unp2_(accp[p][y]);
            d0[tc + 16 * y] = f.x * CSCALE;
            d1[tc + 16 * y] = f.y * CSCALE;
        }
    }
}

// ---------------- rowsum ----------------
__global__ __launch_bounds__(256) void rowsum_kernel(const float* __restrict__ step_p) {
    const int bn = blockIdx.x;
    const int b = bn >> 11;
    const int n = bn & (NN - 1);
    const int L = n + 1;
    const int tid = threadIdx.x;
    const float step = *step_p;
    float4 cn = g_C4[bn];
    cn.x *= step; cn.y *= step; cn.z *= step; cn.w *= step;
    const float4* crow4 = (const float4*)(g_compat + (size_t)bn * NN);
    const float4* cb = g_C4 + b * NN;

    float s = 0.0f;
    const int nv4 = L >> 2;
    for (int m4 = tid; m4 < nv4; m4 += 256) {
        float4 cv = crow4[m4];
        float4 c0 = cb[m4 * 4 + 0], c1 = cb[m4 * 4 + 1], c2 = cb[m4 * 4 + 2], c3 = cb[m4 * 4 + 3];
        s += ex2_(cv.x * (1.0f + cn.x * c0.x + cn.y * c0.y + cn.z * c0.z + cn.w * c0.w));
        s += ex2_(cv.y * (1.0f + cn.x * c1.x + cn.y * c1.y + cn.z * c1.z + cn.w * c1.w));
        s += ex2_(cv.z * (1.0f + cn.x * c2.x + cn.y * c2.y + cn.z * c2.z + cn.w * c2.w));
        s += ex2_(cv.w * (1.0f + cn.x * c3.x + cn.y * c3.y + cn.z * c3.z + cn.w * c3.w));
    }
    {
        int m = (nv4 << 2) + tid;
        if (m < L) {
            float4 cm = cb[m];
            float coef = 1.0f + cn.x * cm.x + cn.y * cm.y + cn.z * cm.z + cn.w * cm.w;
            s += ex2_(g_compat[(size_t)bn * NN + m] * coef);
        }
    }
#pragma unroll
    for (int o = 16; o > 0; o >>= 1) s += __shfl_xor_sync(0xffffffffu, s, o);
    __shared__ float red[8];
    if ((tid & 31) == 0) red[tid >> 5] = s;
    __syncthreads();
    if (tid == 0) {
        float t = red[0] + red[1] + red[2] + red[3] + red[4] + red[5] + red[6] + red[7];
        g_rowinv[bn] = 1.0f / t;
    }
}

// ---------------- colsum ----------------
__global__ __launch_bounds__(256) void colsum_kernel(const float* __restrict__ step_p) {
    const int i = blockIdx.x;
    const int b = blockIdx.y;
    const int chunk = blockIdx.z;
    if (chunk > i) return;
    __shared__ float4 cnS[64];
    __shared__ float4 cmS[64];
    __shared__ float rinvS[64];
    __shared__ float colS[4][64];
    const int tid = threadIdx.x;
    const float step = *step_p;
    if (tid < 64) {
        int gn = b * NN + i * 64 + tid;
        float4 c = g_C4[gn];
        c.x *= step; c.y *= step; c.z *= step; c.w *= step;
        cnS[tid] = c;
        rinvS[tid] = g_rowinv[gn];
    }
    const int c = tid & 63;
    const int rg = tid >> 6;
    for (int j = chunk; j <= i; j += 8) {
        __syncthreads();
        if (tid < 64) cmS[tid] = g_C4[b * NN + j * 64 + tid];
        __syncthreads();
        float4 cm = cmS[c];
        float colsum = 0.0f;
        const float* cbase = g_compat + (size_t)(b * NN + i * 64) * NN + j * 64 + c;
        if (j < i) {
#pragma unroll 4
            for (int rr = 0; rr < 16; rr++) {
                int r = rg + 4 * rr;
                float4 cn = cnS[r];
                float coef = 1.0f + cn.x * cm.x + cn.y * cm.y + cn.z * cm.z + cn.w * cm.w;
                colsum += ex2_(cbase[(size_t)r * NN] * coef) * rinvS[r];
            }
        } else {
            for (int rr = 0; rr < 16; rr++) {
                int r = rg + 4 * rr;
                if (c <= r) {
                    float4 cn = cnS[r];
                    float coef = 1.0f + cn.x * cm.x + cn.y * cm.y + cn.z * cm.z + cn.w * cm.w;
                    colsum += ex2_(cbase[(size_t)r * NN] * coef) * rinvS[r];
                }
            }
        }
        colS[rg][c] = colsum;
        __syncthreads();
        if (tid < 64) {
            float v = colS[0][tid] + colS[1][tid] + colS[2][tid] + colS[3][tid];
            atomicAdd(g_received + b * NN + j * 64 + tid, v);
        }
    }
}

// ---------------- charge update ----------------
__global__ void charge_kernel(int p, const float* __restrict__ decay_p) {
    int idx = blockIdx.x * blockDim.x + threadIdx.x;
    if (idx >= BN) return;
    float decay = *decay_p;
    float r = g_received[idx];
    float* c4 = (float*)g_C4;
    float cprev = (p == 0) ? g_charge0[idx] : c4[idx * 4 + (p - 1)];
    c4[idx * 4 + p] = cprev * (1.0f - decay * sigmoidf_(r - 1.0f));
    g_received[idx] = 0.0f;
}

// ---------------- attn@V: 64x64 tiles, split-m chunks, f32x2 ----------------
__global__ __launch_bounds__(256) void attnv_kernel(const float* __restrict__ step_p) {
    const int i = blockIdx.x;
    const int b = blockIdx.y;
    const int chunk = blockIdx.z;
    if (chunk > i) return;
    const int n0 = i * 64;
    __shared__ float attnS[64][65];
    __shared__ __align__(16) float Vs[64][64];
    __shared__ float4 cnS[64];
    __shared__ float4 cmS[64];
    __shared__ float rinvS[64];
    const int tid = threadIdx.x;
    const float step = *step_p;
    if (tid < 64) {
        int gn = b * NN + n0 + tid;
        float4 cc = g_C4[gn];
        cc.x *= step; cc.y *= step; cc.z *= step; cc.w *= step;
        cnS[tid] = cc;
        rinvS[tid] = g_rowinv[gn];
    }
    u64 accp[4][2];
#pragma unroll
    for (int x = 0; x < 4; x++)
#pragma unroll
        for (int p = 0; p < 2; p++) accp[x][p] = 0ull;
    const int tr = tid >> 4, tc = tid & 15;

    for (int j = chunk; j <= i; j += 4) {
        const int m0 = j * 64;
        __syncthreads();
        if (tid < 64) cmS[tid] = g_C4[b * NN + m0 + tid];
        {
            int m = tid >> 4;
            int d4 = (tid & 15) << 2;
#pragma unroll
            for (int it = 0; it < 4; it++) {
                int mm = m + it * 16;
                float4 v = *(const float4*)(g_V + (size_t)(b * NN + m0 + mm) * DK + d4);
                *(float4*)&Vs[mm][d4] = v;
            }
        }
        __syncthreads();
        for (int q = tid; q < 4096; q += 256) {
            int r = q >> 6, m = q & 63;
            int n = n0 + r, mg = m0 + m;
            float v = 0.0f;
            if (mg <= n) {
                float4 cn = cnS[r], cm = cmS[m];
                float coef = 1.0f + cn.x * cm.x + cn.y * cm.y + cn.z * cm.z + cn.w * cm.w;
                v = ex2_(g_compat[(size_t)(b * NN + n) * NN + mg] * coef) * rinvS[r];
            }
            attnS[r][m] = v;
        }
        __syncthreads();
#pragma unroll 4
        for (int k = 0; k < 64; k++) {
            u64 ad[4], vb[2];
#pragma unroll
            for (int x = 0; x < 4; x++) ad[x] = dup2_(attnS[tr * 4 + x][k]);
            vb[0] = ld2_(&Vs[k][tc * 4]);
            vb[1] = ld2_(&Vs[k][tc * 4 + 2]);
#pragma unroll
            for (int x = 0; x < 4; x++)
#pragma unroll
                for (int p = 0; p < 2; p++) fma2_(accp[x][p], ad[x], vb[p]);
        }
    }
#pragma unroll
    for (int x = 0; x < 4; x++) {
        float* dst = g_attV + (size_t)(b * NN + n0 + tr * 4 + x) * DK + tc * 4;
#pragma unroll
        for (int p = 0; p < 2; p++) {
            float2 f = unp2_(accp[x][p]);
            atomicAdd(dst + 2 * p, f.x);
            atomicAdd(dst + 2 * p + 1, f.y);
        }
    }
}

// ---------------- out = 0.1 * attV @ Wo^T, 64x64 tiles, f32x2 ----------------
__global__ __launch_bounds__(256) void outgemm_kernel(const float* __restrict__ Wo,
                                                      float* __restrict__ out) {
    const int mi = blockIdx.x;
    const int ni = blockIdx.y;
    __shared__ __align__(16) float Ash[64][66];   // [k][r]
    __shared__ float Bsh[64][64];                 // [k][c]
    const int tid = threadIdx.x;
    {
        int r = tid >> 4;
        int kk = (tid & 15) << 2;
#pragma unroll
        for (int it = 0; it < 4; it++) {
            int rr = r + it * 16;
            float4 v = *(const float4*)(g_attV + (size_t)(mi * 64 + rr) * DK + kk);
            Ash[kk + 0][rr] = v.x; Ash[kk + 1][rr] = v.y;
            Ash[kk + 2][rr] = v.z; Ash[kk + 3][rr] = v.w;
        }
        int jc = tid & 63;
        int ks0 = tid >> 6;
        const float* wb = Wo + (size_t)(ni * 64 + jc) * DK;
#pragma unroll
        for (int it = 0; it < 4; it++) {
            int k4 = (ks0 + it * 4) << 2;
            float4 v = *(const float4*)(wb + k4);
            Bsh[k4 + 0][jc] = v.x; Bsh[k4 + 1][jc] = v.y;
            Bsh[k4 + 2][jc] = v.z; Bsh[k4 + 3][jc] = v.w;
        }
    }
    __syncthreads();
    const int tr = tid >> 4, tc = tid & 15;
    u64 accp[2][4];
#pragma unroll
    for (int p = 0; p < 2; p++)
#pragma unroll
        for (int y = 0; y < 4; y++) accp[p][y] = 0ull;
#pragma unroll
    for (int k = 0; k < 64; k++) {
        u64 rap[2], rbd[4];
        rap[0] = ld2_(&Ash[k][tr * 4]);
        rap[1] = ld2_(&Ash[k][tr * 4 + 2]);
#pragma unroll
        for (int y = 0; y < 4; y++) rbd[y] = dup2_(Bsh[k][tc + 16 * y]);
#pragma unroll
        for (int p = 0; p < 2; p++)
#pragma unroll
            for (int y = 0; y < 4; y++) fma2_(accp[p][y], rap[p], rbd[y]);
    }
#pragma unroll
    for (int p = 0; p < 2; p++) {
        size_t b0 = (size_t)(mi * 64 + tr * 4 + 2 * p) * DD + ni * 64;
#pragma unroll
        for (int y = 0; y < 4; y++) {
            float2 f = unp2_(accp[p][y]);
            out[b0 + tc + 16 * y]      = 0.1f * f.x;
            out[b0 + DD + tc + 16 * y] = 0.1f * f.y;
        }
    }
}

// ---------------- launch ----------------
extern "C" void kernel_launch(void* const* d_in, const int* in_sizes, int n_in,
                              void* d_out, int out_size) {
    const float* hidden  = (const float*)d_in[0];
    const float* W1      = (const float*)d_in[1];
    const float* b1      = (const float*)d_in[2];
    const float* W2      = (const float*)d_in[3];
    const float* b2      = (const float*)d_in[4];
    const float* Wq      = (const float*)d_in[5];
    const float* Wk      = (const float*)d_in[6];
    const float* Wc      = (const float*)d_in[7];
    const float* bc      = (const float*)d_in[8];
    const float* Wv      = (const float*)d_in[9];
    const float* Wo      = (const float*)d_in[10];
    const float* step_p  = (const float*)d_in[11];
    const float* decay_p = (const float*)d_in[12];
    float* out = (float*)d_out;

    init_kernel<<<2048, 256>>>();
    gemm1_kernel<<<dim3(128, KCHUNKS), 256>>>(hidden, W1, Wv);
    reduce_kernel<<<4096, 256>>>(b1);
    feat_kernel<<<BN / 8, 256>>>(W2, b2, Wq, Wk, Wc, bc);
    compat_kernel<<<dim3(528, BB), 256>>>();
    for (int p = 0; p < NSTEPS; p++) {
        rowsum_kernel<<<BN, 256>>>(step_p);
        colsum_kernel<<<dim3(NN / 64, BB, 8), 256>>>(step_p);
        charge_kernel<<<BN / 256, 256>>>(p, decay_p);
    }
    rowsum_kernel<<<BN, 256>>>(step_p);
    attnv_kernel<<<dim3(NN / 64, BB, 4), 256>>>(step_p);
    outgemm_kernel<<<dim3(BN / 64, DD / 64), 256>>>(Wo, out);
}

// round 7
// speedup vs baseline: 1.0795x; 1.0777x over previous
#include <cuda_runtime.h>
#include <cuda_bf16.h>
#include <math.h>
#include <stdint.h>

#define BB 4
#define NN 2048
#define DD 1024
#define DK 64
#define BN (BB * NN)
#define NSTEPS 4

// compat is stored pre-scaled by 0.125 * log2(e) so every softmax exp is a bare EX2
#define CSCALE 0.18033688011113063f

__device__ __forceinline__ float ex2_(float x) {
    float y; asm("ex2.approx.ftz.f32 %0, %1;" : "=f"(y) : "f"(x)); return y;
}
__device__ __forceinline__ float sigmoidf_(float x) { return 1.0f / (1.0f + __expf(-x)); }

// ---------------- device scratch ----------------
__device__ float  g_compat[(size_t)BN * NN];          // 64 MB
__device__ float  g_fgelu[BN * 64];
__device__ float  g_V[BN * DK];
__device__ float  g_Q[BN * DK];
__device__ float  g_K[BN * DK];
__device__ float  g_charge0[BN];
__device__ float4 g_C4[BN];
__device__ float  g_received[BN];
__device__ float  g_rowinv[BN];
__device__ float  g_attV[BN * DK];

// ---------------- init ----------------
__global__ void init_kernel() {
    int idx = blockIdx.x * blockDim.x + threadIdx.x;
    if (idx < BN * DK) g_attV[idx] = 0.0f;
    if (idx < BN) { g_received[idx] = 0.0f; g_C4[idx] = make_float4(0.f, 0.f, 0.f, 0.f); }
}

// ================= warp-MMA helpers (mma.sync — portable, no 'a'-target needed) =================
__device__ __forceinline__ uint32_t smem_u32_(const void* p) {
    uint32_t a;
    asm("{ .reg .u64 t; cvta.to.shared.u64 t, %1; cvt.u32.u64 %0, t; }" : "=r"(a) : "l"(p));
    return a;
}
__device__ __forceinline__ void ldsm4_(uint32_t* r, uint32_t addr) {
    asm volatile("ldmatrix.sync.aligned.m8n8.x4.shared.b16 {%0,%1,%2,%3}, [%4];"
        : "=r"(r[0]), "=r"(r[1]), "=r"(r[2]), "=r"(r[3]) : "r"(addr));
}
__device__ __forceinline__ void mma16816_(float* d, const uint32_t* a, uint32_t b0, uint32_t b1) {
    asm volatile("mma.sync.aligned.m16n8k16.row.col.f32.bf16.bf16.f32 "
        "{%0,%1,%2,%3}, {%4,%5,%6,%7}, {%8,%9}, {%0,%1,%2,%3};"
        : "+f"(d[0]), "+f"(d[1]), "+f"(d[2]), "+f"(d[3])
        : "r"(a[0]), "r"(a[1]), "r"(a[2]), "r"(a[3]), "r"(b0), "r"(b1));
}
__device__ __forceinline__ uint32_t pack_bf16x2_(float a, float b) {
    __nv_bfloat162 h = __floats2bfloat162_rn(a, b);
    return *(uint32_t*)&h;
}

// ================= GEMM1 via mma.sync: out[8192,128] = hidden @ [W1;Wv]^T =================
// bf16x3 split (hi*hi + hi*lo + lo*hi). Epilogue fused: cols 0-63 -> gelu(x+b1) -> g_fgelu,
// cols 64-127 -> g_V. CTA: 128 threads, tile M=64 x N=128, K chunks of 32.
__global__ __launch_bounds__(128) void gemm1_mma_kernel(const float* __restrict__ hidden,
                                                        const float* __restrict__ W1,
                                                        const float* __restrict__ Wv,
                                                        const float* __restrict__ b1) {
    // row stride 40 bf16 (80B): ldmatrix 8-row address sets hit distinct bank quads
    __shared__ __align__(16) __nv_bfloat16 sAhi[64][40];
    __shared__ __align__(16) __nv_bfloat16 sAlo[64][40];
    __shared__ __align__(16) __nv_bfloat16 sBhi[128][40];
    __shared__ __align__(16) __nv_bfloat16 sBlo[128][40];

    const int tid = threadIdx.x;
    const int w = tid >> 5, lane = tid & 31;
    const int m0 = blockIdx.x * 64;
    const int mw = (w & 1) * 32;      // warp m-offset within tile
    const int nw = (w >> 1) * 64;     // warp n-offset (0: W1/gelu half, 64: Wv/V half)

    float acc[2][8][4];
#pragma unroll
    for (int mt = 0; mt < 2; mt++)
#pragma unroll
        for (int nt = 0; nt < 8; nt++)
#pragma unroll
            for (int e = 0; e < 4; e++) acc[mt][nt][e] = 0.0f;

    // gmem prefetch registers
    float4 pa[4], pb[8];
    auto loadA = [&](int kc) {
#pragma unroll
        for (int i = 0; i < 4; i++) {
            int idx = tid + i * 128;
            int row = idx >> 3, q = idx & 7;
            pa[i] = *(const float4*)(hidden + (size_t)(m0 + row) * DD + kc * 32 + q * 4);
        }
    };
    auto loadB = [&](int kc) {
#pragma unroll
        for (int i = 0; i < 8; i++) {
            int idx = tid + i * 128;
            int row = idx >> 3, q = idx & 7;
            const float* wr = (row < 64) ? (W1 + (size_t)row * DD) : (Wv + (size_t)(row - 64) * DD);
            pb[i] = *(const float4*)(wr + kc * 32 + q * 4);
        }
    };

    loadA(0); loadB(0);

    for (int kc = 0; kc < 32; kc++) {
        __syncthreads();   // previous chunk's MMAs done reading smem
        // convert + store staged fp32 -> bf16 hi/lo
#pragma unroll
        for (int i = 0; i < 4; i++) {
            int idx = tid + i * 128;
            int row = idx >> 3, q = idx & 7;
            float4 v = pa[i];
            float hx = __bfloat162float(__float2bfloat16(v.x));
            float hy = __bfloat162float(__float2bfloat16(v.y));
            float hz = __bfloat162float(__float2bfloat16(v.z));
            float hw = __bfloat162float(__float2bfloat16(v.w));
            *(uint2*)&sAhi[row][q * 4] = make_uint2(pack_bf16x2_(hx, hy), pack_bf16x2_(hz, hw));
            *(uint2*)&sAlo[row][q * 4] = make_uint2(pack_bf16x2_(v.x - hx, v.y - hy),
                                                   pack_bf16x2_(v.z - hz, v.w - hw));
        }
#pragma unroll
        for (int i = 0; i < 8; i++) {
            int idx = tid + i * 128;
            int row = idx >> 3, q = idx & 7;
            float4 v = pb[i];
            float hx = __bfloat162float(__float2bfloat16(v.x));
            float hy = __bfloat162float(__float2bfloat16(v.y));
            float hz = __bfloat162float(__float2bfloat16(v.z));
            float hw = __bfloat162float(__float2bfloat16(v.w));
            *(uint2*)&sBhi[row][q * 4] = make_uint2(pack_bf16x2_(hx, hy), pack_bf16x2_(hz, hw));
            *(uint2*)&sBlo[row][q * 4] = make_uint2(pack_bf16x2_(v.x - hx, v.y - hy),
                                                   pack_bf16x2_(v.z - hz, v.w - hw));
        }
        if (kc < 31) { loadA(kc + 1); loadB(kc + 1); }   // overlap HBM with MMA below
        __syncthreads();

#pragma unroll
        for (int ks = 0; ks < 32; ks += 16) {
            uint32_t ah[2][4], al[2][4], bh[4][4], bl[4][4];
            const int arow_off = (lane & 15);
            const int akcol = ks + ((lane >> 4) << 3);
#pragma unroll
            for (int mt = 0; mt < 2; mt++) {
                int row = mw + mt * 16 + arow_off;
                ldsm4_(ah[mt], smem_u32_(&sAhi[row][akcol]));
                ldsm4_(al[mt], smem_u32_(&sAlo[row][akcol]));
            }
            const int brow_off = ((lane >> 4) << 3) + (lane & 7);
            const int bkcol = ks + (lane & 8);
#pragma unroll
            for (int p = 0; p < 4; p++) {
                int row = nw + p * 16 + brow_off;
                ldsm4_(bh[p], smem_u32_(&sBhi[row][bkcol]));
                ldsm4_(bl[p], smem_u32_(&sBlo[row][bkcol]));
            }
#pragma unroll
            for (int mt = 0; mt < 2; mt++)
#pragma unroll
                for (int p = 0; p < 4; p++)
#pragma unroll
                    for (int h = 0; h < 2; h++) {
                        float* d = acc[mt][p * 2 + h];
                        mma16816_(d, ah[mt], bh[p][2 * h], bh[p][2 * h + 1]);
                        mma16816_(d, ah[mt], bl[p][2 * h], bl[p][2 * h + 1]);
                        mma16816_(d, al[mt], bh[p][2 * h], bh[p][2 * h + 1]);
                    }
        }
    }

    // epilogue: c-fragment (c0,c1)=row, (c2,c3)=row+8; cols (lane&3)*2, +1
#pragma unroll
    for (int mt = 0; mt < 2; mt++)
#pragma unroll
        for (int nt = 0; nt < 8; nt++) {
            int r = m0 + mw + mt * 16 + (lane >> 2);
            int c = nw + nt * 8 + (lane & 3) * 2;
#pragma unroll
            for (int half = 0; half < 2; half++) {
                int row = r + half * 8;
                float v0 = acc[mt][nt][half * 2 + 0];
                float v1 = acc[mt][nt][half * 2 + 1];
                if (c < 64) {
                    float x0 = v0 + b1[c];
                    float x1 = v1 + b1[c + 1];
                    g_fgelu[row * 64 + c]     = 0.5f * x0 * (1.0f + erff(x0 * 0.7071067811865475f));
                    g_fgelu[row * 64 + c + 1] = 0.5f * x1 * (1.0f + erff(x1 * 0.7071067811865475f));
                } else {
                    g_V[row * DK + (c - 64)]     = v0;
                    g_V[row * DK + (c - 64) + 1] = v1;
                }
            }
        }
}

// ---------------- feature net: warp-per-row (validated) ----------------
__global__ __launch_bounds__(256) void feat_kernel(const float* __restrict__ W2,
                                                   const float* __restrict__ b2,
                                                   const float* __restrict__ Wq,
                                                   const float* __restrict__ Wk,
                                                   const float* __restrict__ Wc,
                                                   const float* __restrict__ bc) {
    __shared__ float W2s[28][65];
    __shared__ float Wqs[64][29];
    __shared__ float Wks[64][29];
    __shared__ float fsS[8][66];
    __shared__ float featS[8][29];
    __shared__ float b2s[28], WcS[28];
    const int tid = threadIdx.x;
    const int w = tid >> 5, lane = tid & 31;
    const int row = blockIdx.x * 8 + w;

    for (int idx = tid; idx < 28 * 64; idx += 256) W2s[idx >> 6][idx & 63] = W2[idx];
    for (int idx = tid; idx < 64 * 28; idx += 256) {
        int d = idx / 28, k = idx - d * 28;
        Wqs[d][k] = Wq[idx];
        Wks[d][k] = Wk[idx];
    }
    if (tid < 28) { b2s[tid] = b2[tid]; WcS[tid] = Wc[tid]; }
    fsS[w][lane]      = g_fgelu[row * 64 + lane];
    fsS[w][lane + 32] = g_fgelu[row * 64 + lane + 32];
    __syncthreads();

    if (lane < 28) {
        float s = b2s[lane];
#pragma unroll
        for (int k = 0; k < 64; k++) s += W2s[lane][k] * fsS[w][k];
        featS[w][lane] = sigmoidf_(s);
    }
    __syncwarp();

    {
        float q0 = 0.f, k0 = 0.f, q1 = 0.f, k1 = 0.f;
        int d0 = lane, d1 = lane + 32;
#pragma unroll
        for (int k = 0; k < 28; k++) {
            float f = featS[w][k];
            q0 += Wqs[d0][k] * f; k0 += Wks[d0][k] * f;
            q1 += Wqs[d1][k] * f; k1 += Wks[d1][k] * f;
        }
        g_Q[row * DK + d0] = q0; g_K[row * DK + d0] = k0;
        g_Q[row * DK + d1] = q1; g_K[row * DK + d1] = k1;
    }
    if (lane == 0) {
        float s = bc[0];
#pragma unroll
        for (int k = 0; k < 28; k++) s += WcS[k] * featS[w][k];
        g_charge0[row] = sigmoidf_(s);
    }
}

// ---------------- compat = Q K^T * CSCALE, 64x64 causal tiles (R2 scalar) ----------------
__global__ __launch_bounds__(256) void compat_kernel() {
    const int b = blockIdx.y;
    int t = blockIdx.x;
    int i = 0;
    while ((i + 1) * (i + 2) / 2 <= t) i++;
    int j = t - i * (i + 1) / 2;

    __shared__ float Qsh[64][65];
    __shared__ float Ksh[64][64];
    const int tid = threadIdx.x;
    {
        int r = tid >> 4;
        int kk = (tid & 15) << 2;
#pragma unroll
        for (int it = 0; it < 4; it++) {
            int rr = r + it * 16;
            float4 v = *(const float4*)(g_Q + (size_t)(b * NN + i * 64 + rr) * DK + kk);
            Qsh[kk + 0][rr] = v.x; Qsh[kk + 1][rr] = v.y;
            Qsh[kk + 2][rr] = v.z; Qsh[kk + 3][rr] = v.w;
        }
        int jc = tid & 63;
        int ks0 = tid >> 6;
        const float* kb = g_K + (size_t)(b * NN + j * 64 + jc) * DK;
#pragma unroll
        for (int it = 0; it < 4; it++) {
            int k4 = (ks0 + it * 4) << 2;
            float4 v = *(const float4*)(kb + k4);
            Ksh[k4 + 0][jc] = v.x; Ksh[k4 + 1][jc] = v.y;
            Ksh[k4 + 2][jc] = v.z; Ksh[k4 + 3][jc] = v.w;
        }
    }
    __syncthreads();
    const int tr = tid >> 4, tc = tid & 15;
    float acc[4][4] = {{0.f}};
#pragma unroll
    for (int k = 0; k < 64; k++) {
        float ra[4], rb[4];
#pragma unroll
        for (int x = 0; x < 4; x++) ra[x] = Qsh[k][tr * 4 + x];
#pragma unroll
        for (int y = 0; y < 4; y++) rb[y] = Ksh[k][tc + 16 * y];
#pragma unroll
        for (int x = 0; x < 4; x++)
#pragma unroll
            for (int y = 0; y < 4; y++) acc[x][y] += ra[x] * rb[y];
    }
#pragma unroll
    for (int x = 0; x < 4; x++) {
        int n = i * 64 + tr * 4 + x;
        float* dst = g_compat + (size_t)(b * NN + n) * NN + j * 64;
#pragma unroll
        for (int y = 0; y < 4; y++) dst[tc + 16 * y] = acc[x][y] * CSCALE;
    }
}

// ---------------- rowsum ----------------
__global__ __launch_bounds__(256) void rowsum_kernel(const float* __restrict__ step_p) {
    const int bn = blockIdx.x;
    const int b = bn >> 11;
    const int n = bn & (NN - 1);
    const int L = n + 1;
    const int tid = threadIdx.x;
    const float step = *step_p;
    float4 cn = g_C4[bn];
    cn.x *= step; cn.y *= step; cn.z *= step; cn.w *= step;
    const float4* crow4 = (const float4*)(g_compat + (size_t)bn * NN);
    const float4* cb = g_C4 + b * NN;

    float s = 0.0f;
    const int nv4 = L >> 2;
    for (int m4 = tid; m4 < nv4; m4 += 256) {
        float4 cv = crow4[m4];
        float4 c0 = cb[m4 * 4 + 0], c1 = cb[m4 * 4 + 1], c2 = cb[m4 * 4 + 2], c3 = cb[m4 * 4 + 3];
        s += ex2_(cv.x * (1.0f + cn.x * c0.x + cn.y * c0.y + cn.z * c0.z + cn.w * c0.w));
        s += ex2_(cv.y * (1.0f + cn.x * c1.x + cn.y * c1.y + cn.z * c1.z + cn.w * c1.w));
        s += ex2_(cv.z * (1.0f + cn.x * c2.x + cn.y * c2.y + cn.z * c2.z + cn.w * c2.w));
        s += ex2_(cv.w * (1.0f + cn.x * c3.x + cn.y * c3.y + cn.z * c3.z + cn.w * c3.w));
    }
    {
        int m = (nv4 << 2) + tid;
        if (m < L) {
            float4 cm = cb[m];
            float coef = 1.0f + cn.x * cm.x + cn.y * cm.y + cn.z * cm.z + cn.w * cm.w;
            s += ex2_(g_compat[(size_t)bn * NN + m] * coef);
        }
    }
#pragma unroll
    for (int o = 16; o > 0; o >>= 1) s += __shfl_xor_sync(0xffffffffu, s, o);
    __shared__ float red[8];
    if ((tid & 31) == 0) red[tid >> 5] = s;
    __syncthreads();
    if (tid == 0) {
        float t = red[0] + red[1] + red[2] + red[3] + red[4] + red[5] + red[6] + red[7];
        g_rowinv[bn] = 1.0f / t;
    }
}

// ---------------- colsum ----------------
__global__ __launch_bounds__(256) void colsum_kernel(const float* __restrict__ step_p) {
    const int i = blockIdx.x;
    const int b = blockIdx.y;
    const int chunk = blockIdx.z;
    if (chunk > i) return;
    __shared__ float4 cnS[64];
    __shared__ float4 cmS[64];
    __shared__ float rinvS[64];
    __shared__ float colS[4][64];
    const int tid = threadIdx.x;
    const float step = *step_p;
    if (tid < 64) {
        int gn = b * NN + i * 64 + tid;
        float4 c = g_C4[gn];
        c.x *= step; c.y *= step; c.z *= step; c.w *= step;
        cnS[tid] = c;
        rinvS[tid] = g_rowinv[gn];
    }
    const int c = tid & 63;
    const int rg = tid >> 6;
    for (int j = chunk; j <= i; j += 8) {
        __syncthreads();
        if (tid < 64) cmS[tid] = g_C4[b * NN + j * 64 + tid];
        __syncthreads();
        float4 cm = cmS[c];
        float colsum = 0.0f;
        const float* cbase = g_compat + (size_t)(b * NN + i * 64) * NN + j * 64 + c;
        if (j < i) {
#pragma unroll 4
            for (int rr = 0; rr < 16; rr++) {
                int r = rg + 4 * rr;
                float4 cn = cnS[r];
                float coef = 1.0f + cn.x * cm.x + cn.y * cm.y + cn.z * cm.z + cn.w * cm.w;
                colsum += ex2_(cbase[(size_t)r * NN] * coef) * rinvS[r];
            }
        } else {
            for (int rr = 0; rr < 16; rr++) {
                int r = rg + 4 * rr;
                if (c <= r) {
                    float4 cn = cnS[r];
                    float coef = 1.0f + cn.x * cm.x + cn.y * cm.y + cn.z * cm.z + cn.w * cm.w;
                    colsum += ex2_(cbase[(size_t)r * NN] * coef) * rinvS[r];
                }
            }
        }
        colS[rg][c] = colsum;
        __syncthreads();
        if (tid < 64) {
            float v = colS[0][tid] + colS[1][tid] + colS[2][tid] + colS[3][tid];
            atomicAdd(g_received + b * NN + j * 64 + tid, v);
        }
    }
}

// ---------------- charge update ----------------
__global__ void charge_kernel(int p, const float* __restrict__ decay_p) {
    int idx = blockIdx.x * blockDim.x + threadIdx.x;
    if (idx >= BN) return;
    float decay = *decay_p;
    float r = g_received[idx];
    float* c4 = (float*)g_C4;
    float cprev = (p == 0) ? g_charge0[idx] : c4[idx * 4 + (p - 1)];
    c4[idx * 4 + p] = cprev * (1.0f - decay * sigmoidf_(r - 1.0f));
    g_received[idx] = 0.0f;
}

// ---------------- attn@V: 64x64 tiles, split-m chunks (R2 scalar) ----------------
__global__ __launch_bounds__(256) void attnv_kernel(const float* __restrict__ step_p) {
    const int i = blockIdx.x;
    const int b = blockIdx.y;
    const int chunk = blockIdx.z;
    if (chunk > i) return;
    const int n0 = i * 64;
    __shared__ float attnS[64][65];
    __shared__ float Vs[64][64];
    __shared__ float4 cnS[64];
    __shared__ float4 cmS[64];
    __shared__ float rinvS[64];
    const int tid = threadIdx.x;
    const float step = *step_p;
    if (tid < 64) {
        int gn = b * NN + n0 + tid;
        float4 cc = g_C4[gn];
        cc.x *= step; cc.y *= step; cc.z *= step; cc.w *= step;
        cnS[tid] = cc;
        rinvS[tid] = g_rowinv[gn];
    }
    float acc[4][4] = {{0.f}};
    const int tr = tid >> 4, tc = tid & 15;

    for (int j = chunk; j <= i; j += 4) {
        const int m0 = j * 64;
        __syncthreads();
        if (tid < 64) cmS[tid] = g_C4[b * NN + m0 + tid];
        {
            int m = tid >> 4;
            int d4 = (tid & 15) << 2;
#pragma unroll
            for (int it = 0; it < 4; it++) {
                int mm = m + it * 16;
                float4 v = *(const float4*)(g_V + (size_t)(b * NN + m0 + mm) * DK + d4);
                Vs[mm][d4 + 0] = v.x; Vs[mm][d4 + 1] = v.y;
                Vs[mm][d4 + 2] = v.z; Vs[mm][d4 + 3] = v.w;
            }
        }
        __syncthreads();
        for (int qq = tid; qq < 4096; qq += 256) {
            int r = qq >> 6, m = qq & 63;
            int n = n0 + r, mg = m0 + m;
            float v = 0.0f;
            if (mg <= n) {
                float4 cn = cnS[r], cm = cmS[m];
                float coef = 1.0f + cn.x * cm.x + cn.y * cm.y + cn.z * cm.z + cn.w * cm.w;
                v = ex2_(g_compat[(size_t)(b * NN + n) * NN + mg] * coef) * rinvS[r];
            }
            attnS[r][m] = v;
        }
        __syncthreads();
#pragma unroll 8
        for (int k = 0; k < 64; k++) {
            float ra[4], rb[4];
#pragma unroll
            for (int x = 0; x < 4; x++) ra[x] = attnS[tr * 4 + x][k];
#pragma unroll
            for (int y = 0; y < 4; y++) rb[y] = Vs[k][tc + 16 * y];
#pragma unroll
            for (int x = 0; x < 4; x++)
#pragma unroll
                for (int y = 0; y < 4; y++) acc[x][y] += ra[x] * rb[y];
        }
    }
#pragma unroll
    for (int x = 0; x < 4; x++) {
        float* dst = g_attV + (size_t)(b * NN + n0 + tr * 4 + x) * DK;
#pragma unroll
        for (int y = 0; y < 4; y++) atomicAdd(dst + tc + 16 * y, acc[x][y]);
    }
}

// ---------------- out = 0.1 * attV @ Wo^T (R2 scalar) ----------------
__global__ __launch_bounds__(256) void outgemm_kernel(const float* __restrict__ Wo,
                                                      float* __restrict__ out) {
    const int mi = blockIdx.x;
    const int ni = blockIdx.y;
    __shared__ float Ash[64][65];
    __shared__ float Bsh[64][64];
    const int tid = threadIdx.x;
    {
        int r = tid >> 4;
        int kk = (tid & 15) << 2;
#pragma unroll
        for (int it = 0; it < 4; it++) {
            int rr = r + it * 16;
            float4 v = *(const float4*)(g_attV + (size_t)(mi * 64 + rr) * DK + kk);
            Ash[kk + 0][rr] = v.x; Ash[kk + 1][rr] = v.y;
            Ash[kk + 2][rr] = v.z; Ash[kk + 3][rr] = v.w;
        }
        int jc = tid & 63;
        int ks0 = tid >> 6;
        const float* wb = Wo + (size_t)(ni * 64 + jc) * DK;
#pragma unroll
        for (int it = 0; it < 4; it++) {
            int k4 = (ks0 + it * 4) << 2;
            float4 v = *(const float4*)(wb + k4);
            Bsh[k4 + 0][jc] = v.x; Bsh[k4 + 1][jc] = v.y;
            Bsh[k4 + 2][jc] = v.z; Bsh[k4 + 3][jc] = v.w;
        }
    }
    __syncthreads();
    const int tr = tid >> 4, tc = tid & 15;
    float acc[4][4] = {{0.f}};
#pragma unroll
    for (int k = 0; k < 64; k++) {
        float ra[4], rb[4];
#pragma unroll
        for (int x = 0; x < 4; x++) ra[x] = Ash[k][tr * 4 + x];
#pragma unroll
        for (int y = 0; y < 4; y++) rb[y] = Bsh[k][tc + 16 * y];
#pragma unroll
        for (int x = 0; x < 4; x++)
#pragma unroll
            for (int y = 0; y < 4; y++) acc[x][y] += ra[x] * rb[y];
    }
#pragma unroll
    for (int x = 0; x < 4; x++) {
        size_t base = (size_t)(mi * 64 + tr * 4 + x) * DD + ni * 64;
#pragma unroll
        for (int y = 0; y < 4; y++) out[base + tc + 16 * y] = 0.1f * acc[x][y];
    }
}

// ---------------- launch ----------------
extern "C" void kernel_launch(void* const* d_in, const int* in_sizes, int n_in,
                              void* d_out, int out_size) {
    const float* hidden  = (const float*)d_in[0];
    const float* W1      = (const float*)d_in[1];
    const float* b1      = (const float*)d_in[2];
    const float* W2      = (const float*)d_in[3];
    const float* b2      = (const float*)d_in[4];
    const float* Wq      = (const float*)d_in[5];
    const float* Wk      = (const float*)d_in[6];
    const float* Wc      = (const float*)d_in[7];
    const float* bc      = (const float*)d_in[8];
    const float* Wv      = (const float*)d_in[9];
    const float* Wo      = (const float*)d_in[10];
    const float* step_p  = (const float*)d_in[11];
    const float* decay_p = (const float*)d_in[12];
    float* out = (float*)d_out;

    init_kernel<<<2048, 256>>>();
    gemm1_mma_kernel<<<128, 128>>>(hidden, W1, Wv, b1);
    feat_kernel<<<BN / 8, 256>>>(W2, b2, Wq, Wk, Wc, bc);
    compat_kernel<<<dim3(528, BB), 256>>>();
    for (int p = 0; p < NSTEPS; p++) {
        rowsum_kernel<<<BN, 256>>>(step_p);
        colsum_kernel<<<dim3(NN / 64, BB, 8), 256>>>(step_p);
        charge_kernel<<<BN / 256, 256>>>(p, decay_p);
    }
    rowsum_kernel<<<BN, 256>>>(step_p);
    attnv_kernel<<<dim3(NN / 64, BB, 4), 256>>>(step_p);
    outgemm_kernel<<<dim3(BN / 64, DD / 64), 256>>>(Wo, out);
}

// round 8
// speedup vs baseline: 1.0909x; 1.0106x over previous
#include <cuda_runtime.h>
#include <cuda_bf16.h>
#include <math.h>
#include <stdint.h>

#define BB 4
#define NN 2048
#define DD 1024
#define DK 64
#define BN (BB * NN)
#define NSTEPS 4

// compat is stored pre-scaled by 0.125 * log2(e) so every softmax exp is a bare EX2
#define CSCALE 0.18033688011113063f

__device__ __forceinline__ float ex2_(float x) {
    float y; asm("ex2.approx.ftz.f32 %0, %1;" : "=f"(y) : "f"(x)); return y;
}
__device__ __forceinline__ float sigmoidf_(float x) { return 1.0f / (1.0f + __expf(-x)); }

// ---------------- device scratch ----------------
__device__ float  g_compat[(size_t)BN * NN];          // 64 MB
__device__ float  g_part[(size_t)2 * BN * 128];       // split-k fp32 partials
__device__ __nv_bfloat16 g_Whi[128 * DD];             // precomputed weight split
__device__ __nv_bfloat16 g_Wlo[128 * DD];
__device__ float  g_fgelu[BN * 64];
__device__ float  g_V[BN * DK];
__device__ float  g_Q[BN * DK];
__device__ float  g_K[BN * DK];
__device__ float  g_charge0[BN];
__device__ float4 g_C4[BN];
__device__ float  g_received[BN];
__device__ float  g_rowinv[BN];
__device__ float  g_attV[BN * DK];

// ---------------- init ----------------
__global__ void init_kernel() {
    int idx = blockIdx.x * blockDim.x + threadIdx.x;
    if (idx < BN * DK) g_attV[idx] = 0.0f;
    if (idx < BN) { g_received[idx] = 0.0f; g_C4[idx] = make_float4(0.f, 0.f, 0.f, 0.f); }
}

// ---------------- precompute W = [W1;Wv] bf16 hi/lo split ----------------
__global__ void wsplit_kernel(const float* __restrict__ W1, const float* __restrict__ Wv) {
    int idx = blockIdx.x * blockDim.x + threadIdx.x;   // 0 .. 128*1024-1
    if (idx >= 128 * DD) return;
    int row = idx >> 10;
    float v = (row < 64) ? W1[idx] : Wv[idx - 64 * DD];
    __nv_bfloat16 h = __float2bfloat16(v);
    g_Whi[idx] = h;
    g_Wlo[idx] = __float2bfloat16(v - __bfloat162float(h));
}

// ================= warp-MMA helpers =================
__device__ __forceinline__ uint32_t smem_u32_(const void* p) {
    uint32_t a;
    asm("{ .reg .u64 t; cvta.to.shared.u64 t, %1; cvt.u32.u64 %0, t; }" : "=r"(a) : "l"(p));
    return a;
}
__device__ __forceinline__ void ldsm4_(uint32_t* r, uint32_t addr) {
    asm volatile("ldmatrix.sync.aligned.m8n8.x4.shared.b16 {%0,%1,%2,%3}, [%4];"
        : "=r"(r[0]), "=r"(r[1]), "=r"(r[2]), "=r"(r[3]) : "r"(addr));
}
__device__ __forceinline__ void mma16816_(float* d, const uint32_t* a, uint32_t b0, uint32_t b1) {
    asm volatile("mma.sync.aligned.m16n8k16.row.col.f32.bf16.bf16.f32 "
        "{%0,%1,%2,%3}, {%4,%5,%6,%7}, {%8,%9}, {%0,%1,%2,%3};"
        : "+f"(d[0]), "+f"(d[1]), "+f"(d[2]), "+f"(d[3])
        : "r"(a[0]), "r"(a[1]), "r"(a[2]), "r"(a[3]), "r"(b0), "r"(b1));
}
__device__ __forceinline__ uint32_t pack_bf16x2_(float a, float b) {
    __nv_bfloat162 h = __floats2bfloat162_rn(a, b);
    return *(uint32_t*)&h;
}

// ================= GEMM1 via mma.sync v2: split-K x2, 256 threads, 8 warps =================
// CTA tile M=64 x N=128 x Khalf=512 (16 chunks of 32). Warp tile m32 x n32.
// bf16x3 split: Ahi*Bhi + Ahi*Blo + Alo*Bhi. Writes fp32 partials.
__global__ __launch_bounds__(256) void gemm1_mma2_kernel(const float* __restrict__ hidden) {
    __shared__ __align__(16) __nv_bfloat16 sAhi[64][40];
    __shared__ __align__(16) __nv_bfloat16 sAlo[64][40];
    __shared__ __align__(16) __nv_bfloat16 sBhi[128][40];
    __shared__ __align__(16) __nv_bfloat16 sBlo[128][40];

    const int tid = threadIdx.x;
    const int w = tid >> 5, lane = tid & 31;
    const int m0 = blockIdx.x * 64;
    const int kbase = blockIdx.y * 512;
    const int mw = (w & 1) * 32;
    const int nw = (w >> 1) * 32;

    float acc[2][4][4];
#pragma unroll
    for (int mt = 0; mt < 2; mt++)
#pragma unroll
        for (int nt = 0; nt < 4; nt++)
#pragma unroll
            for (int e = 0; e < 4; e++) acc[mt][nt][e] = 0.0f;

    float4 pa[2];
    uint4 pbh[2], pbl[2];
    auto loadA = [&](int kc) {
#pragma unroll
        for (int i = 0; i < 2; i++) {
            int idx = tid + i * 256;
            int row = idx >> 3, q = idx & 7;
            pa[i] = *(const float4*)(hidden + (size_t)(m0 + row) * DD + kbase + kc * 32 + q * 4);
        }
    };
    auto loadB = [&](int kc) {
#pragma unroll
        for (int i = 0; i < 2; i++) {
            int idx = tid + i * 256;
            int row = idx >> 2, q = idx & 3;
            pbh[i] = *(const uint4*)(g_Whi + (size_t)row * DD + kbase + kc * 32 + q * 8);
            pbl[i] = *(const uint4*)(g_Wlo + (size_t)row * DD + kbase + kc * 32 + q * 8);
        }
    };

    loadA(0); loadB(0);

    for (int kc = 0; kc < 16; kc++) {
        __syncthreads();
#pragma unroll
        for (int i = 0; i < 2; i++) {
            int idx = tid + i * 256;
            int row = idx >> 3, q = idx & 7;
            float4 v = pa[i];
            float hx = __bfloat162float(__float2bfloat16(v.x));
            float hy = __bfloat162float(__float2bfloat16(v.y));
            float hz = __bfloat162float(__float2bfloat16(v.z));
            float hw = __bfloat162float(__float2bfloat16(v.w));
            *(uint2*)&sAhi[row][q * 4] = make_uint2(pack_bf16x2_(hx, hy), pack_bf16x2_(hz, hw));
            *(uint2*)&sAlo[row][q * 4] = make_uint2(pack_bf16x2_(v.x - hx, v.y - hy),
                                                   pack_bf16x2_(v.z - hz, v.w - hw));
        }
#pragma unroll
        for (int i = 0; i < 2; i++) {
            int idx = tid + i * 256;
            int row = idx >> 2, q = idx & 3;
            *(uint4*)&sBhi[row][q * 8] = pbh[i];
            *(uint4*)&sBlo[row][q * 8] = pbl[i];
        }
        if (kc < 15) { loadA(kc + 1); loadB(kc + 1); }
        __syncthreads();

#pragma unroll
        for (int ks = 0; ks < 32; ks += 16) {
            uint32_t ah[2][4], al[2][4], bh[2][4], bl[2][4];
            const int arow = (lane & 15);
            const int akcol = ks + ((lane >> 4) << 3);
#pragma unroll
            for (int mt = 0; mt < 2; mt++) {
                int row = mw + mt * 16 + arow;
                ldsm4_(ah[mt], smem_u32_(&sAhi[row][akcol]));
                ldsm4_(al[mt], smem_u32_(&sAlo[row][akcol]));
            }
            const int brow = ((lane >> 4) << 3) + (lane & 7);
            const int bkcol = ks + (lane & 8);
#pragma unroll
            for (int p = 0; p < 2; p++) {
                int row = nw + p * 16 + brow;
                ldsm4_(bh[p], smem_u32_(&sBhi[row][bkcol]));
                ldsm4_(bl[p], smem_u32_(&sBlo[row][bkcol]));
            }
#pragma unroll
            for (int mt = 0; mt < 2; mt++)
#pragma unroll
                for (int p = 0; p < 2; p++)
#pragma unroll
                    for (int h = 0; h < 2; h++) {
                        float* d = acc[mt][p * 2 + h];
                        mma16816_(d, ah[mt], bh[p][2 * h], bh[p][2 * h + 1]);
                        mma16816_(d, ah[mt], bl[p][2 * h], bl[p][2 * h + 1]);
                        mma16816_(d, al[mt], bh[p][2 * h], bh[p][2 * h + 1]);
                    }
        }
    }

    float* pbase = g_part + (size_t)blockIdx.y * BN * 128;
#pragma unroll
    for (int mt = 0; mt < 2; mt++)
#pragma unroll
        for (int nt = 0; nt < 4; nt++) {
            int r = m0 + mw + mt * 16 + (lane >> 2);
            int c = nw + nt * 8 + (lane & 3) * 2;
#pragma unroll
            for (int half = 0; half < 2; half++) {
                int row = r + half * 8;
                *(float2*)(pbase + (size_t)row * 128 + c) =
                    make_float2(acc[mt][nt][half * 2 + 0], acc[mt][nt][half * 2 + 1]);
            }
        }
}

// ---------------- reduce split-k x2 + fused gelu ----------------
__global__ __launch_bounds__(256) void reduce2_kernel(const float* __restrict__ b1) {
    int idx = blockIdx.x * blockDim.x + threadIdx.x;
    if (idx >= BN * 128) return;
    float s = g_part[idx] + g_part[idx + (size_t)BN * 128];
    int row = idx >> 7, c = idx & 127;
    if (c < 64) {
        float x = s + b1[c];
        g_fgelu[row * 64 + c] = 0.5f * x * (1.0f + erff(x * 0.7071067811865475f));
    } else {
        g_V[row * DK + (c - 64)] = s;
    }
}

// ---------------- feature net: warp-per-row (validated) ----------------
__global__ __launch_bounds__(256) void feat_kernel(const float* __restrict__ W2,
                                                   const float* __restrict__ b2,
                                                   const float* __restrict__ Wq,
                                                   const float* __restrict__ Wk,
                                                   const float* __restrict__ Wc,
                                                   const float* __restrict__ bc) {
    __shared__ float W2s[28][65];
    __shared__ float Wqs[64][29];
    __shared__ float Wks[64][29];
    __shared__ float fsS[8][66];
    __shared__ float featS[8][29];
    __shared__ float b2s[28], WcS[28];
    const int tid = threadIdx.x;
    const int w = tid >> 5, lane = tid & 31;
    const int row = blockIdx.x * 8 + w;

    for (int idx = tid; idx < 28 * 64; idx += 256) W2s[idx >> 6][idx & 63] = W2[idx];
    for (int idx = tid; idx < 64 * 28; idx += 256) {
        int d = idx / 28, k = idx - d * 28;
        Wqs[d][k] = Wq[idx];
        Wks[d][k] = Wk[idx];
    }
    if (tid < 28) { b2s[tid] = b2[tid]; WcS[tid] = Wc[tid]; }
    fsS[w][lane]      = g_fgelu[row * 64 + lane];
    fsS[w][lane + 32] = g_fgelu[row * 64 + lane + 32];
    __syncthreads();

    if (lane < 28) {
        float s = b2s[lane];
#pragma unroll
        for (int k = 0; k < 64; k++) s += W2s[lane][k] * fsS[w][k];
        featS[w][lane] = sigmoidf_(s);
    }
    __syncwarp();

    {
        float q0 = 0.f, k0 = 0.f, q1 = 0.f, k1 = 0.f;
        int d0 = lane, d1 = lane + 32;
#pragma unroll
        for (int k = 0; k < 28; k++) {
            float f = featS[w][k];
            q0 += Wqs[d0][k] * f; k0 += Wks[d0][k] * f;
            q1 += Wqs[d1][k] * f; k1 += Wks[d1][k] * f;
        }
        g_Q[row * DK + d0] = q0; g_K[row * DK + d0] = k0;
        g_Q[row * DK + d1] = q1; g_K[row * DK + d1] = k1;
    }
    if (lane == 0) {
        float s = bc[0];
#pragma unroll
        for (int k = 0; k < 28; k++) s += WcS[k] * featS[w][k];
        g_charge0[row] = sigmoidf_(s);
    }
}

// ---------------- compat = Q K^T * CSCALE, 64x64 causal tiles (R2 scalar) ----------------
__global__ __launch_bounds__(256) void compat_kernel() {
    const int b = blockIdx.y;
    int t = blockIdx.x;
    int i = 0;
    while ((i + 1) * (i + 2) / 2 <= t) i++;
    int j = t - i * (i + 1) / 2;

    __shared__ float Qsh[64][65];
    __shared__ float Ksh[64][64];
    const int tid = threadIdx.x;
    {
        int r = tid >> 4;
        int kk = (tid & 15) << 2;
#pragma unroll
        for (int it = 0; it < 4; it++) {
            int rr = r + it * 16;
            float4 v = *(const float4*)(g_Q + (size_t)(b * NN + i * 64 + rr) * DK + kk);
            Qsh[kk + 0][rr] = v.x; Qsh[kk + 1][rr] = v.y;
            Qsh[kk + 2][rr] = v.z; Qsh[kk + 3][rr] = v.w;
        }
        int jc = tid & 63;
        int ks0 = tid >> 6;
        const float* kb = g_K + (size_t)(b * NN + j * 64 + jc) * DK;
#pragma unroll
        for (int it = 0; it < 4; it++) {
            int k4 = (ks0 + it * 4) << 2;
            float4 v = *(const float4*)(kb + k4);
            Ksh[k4 + 0][jc] = v.x; Ksh[k4 + 1][jc] = v.y;
            Ksh[k4 + 2][jc] = v.z; Ksh[k4 + 3][jc] = v.w;
        }
    }
    __syncthreads();
    const int tr = tid >> 4, tc = tid & 15;
    float acc[4][4] = {{0.f}};
#pragma unroll
    for (int k = 0; k < 64; k++) {
        float ra[4], rb[4];
#pragma unroll
        for (int x = 0; x < 4; x++) ra[x] = Qsh[k][tr * 4 + x];
#pragma unroll
        for (int y = 0; y < 4; y++) rb[y] = Ksh[k][tc + 16 * y];
#pragma unroll
        for (int x = 0; x < 4; x++)
#pragma unroll
            for (int y = 0; y < 4; y++) acc[x][y] += ra[x] * rb[y];
    }
#pragma unroll
    for (int x = 0; x < 4; x++) {
        int n = i * 64 + tr * 4 + x;
        float* dst = g_compat + (size_t)(b * NN + n) * NN + j * 64;
#pragma unroll
        for (int y = 0; y < 4; y++) dst[tc + 16 * y] = acc[x][y] * CSCALE;
    }
}

// ---------------- rowsum ----------------
__global__ __launch_bounds__(256) void rowsum_kernel(const float* __restrict__ step_p) {
    const int bn = blockIdx.x;
    const int b = bn >> 11;
    const int n = bn & (NN - 1);
    const int L = n + 1;
    const int tid = threadIdx.x;
    const float step = *step_p;
    float4 cn = g_C4[bn];
    cn.x *= step; cn.y *= step; cn.z *= step; cn.w *= step;
    const float4* crow4 = (const float4*)(g_compat + (size_t)bn * NN);
    const float4* cb = g_C4 + b * NN;

    float s = 0.0f;
    const int nv4 = L >> 2;
    for (int m4 = tid; m4 < nv4; m4 += 256) {
        float4 cv = crow4[m4];
        float4 c0 = cb[m4 * 4 + 0], c1 = cb[m4 * 4 + 1], c2 = cb[m4 * 4 + 2], c3 = cb[m4 * 4 + 3];
        s += ex2_(cv.x * (1.0f + cn.x * c0.x + cn.y * c0.y + cn.z * c0.z + cn.w * c0.w));
        s += ex2_(cv.y * (1.0f + cn.x * c1.x + cn.y * c1.y + cn.z * c1.z + cn.w * c1.w));
        s += ex2_(cv.z * (1.0f + cn.x * c2.x + cn.y * c2.y + cn.z * c2.z + cn.w * c2.w));
        s += ex2_(cv.w * (1.0f + cn.x * c3.x + cn.y * c3.y + cn.z * c3.z + cn.w * c3.w));
    }
    {
        int m = (nv4 << 2) + tid;
        if (m < L) {
            float4 cm = cb[m];
            float coef = 1.0f + cn.x * cm.x + cn.y * cm.y + cn.z * cm.z + cn.w * cm.w;
            s += ex2_(g_compat[(size_t)bn * NN + m] * coef);
        }
    }
#pragma unroll
    for (int o = 16; o > 0; o >>= 1) s += __shfl_xor_sync(0xffffffffu, s, o);
    __shared__ float red[8];
    if ((tid & 31) == 0) red[tid >> 5] = s;
    __syncthreads();
    if (tid == 0) {
        float t = red[0] + red[1] + red[2] + red[3] + red[4] + red[5] + red[6] + red[7];
        g_rowinv[bn] = 1.0f / t;
    }
}

// ---------------- colsum ----------------
__global__ __launch_bounds__(256) void colsum_kernel(const float* __restrict__ step_p) {
    const int i = blockIdx.x;
    const int b = blockIdx.y;
    const int chunk = blockIdx.z;
    if (chunk > i) return;
    __shared__ float4 cnS[64];
    __shared__ float4 cmS[64];
    __shared__ float rinvS[64];
    __shared__ float colS[4][64];
    const int tid = threadIdx.x;
    const float step = *step_p;
    if (tid < 64) {
        int gn = b * NN + i * 64 + tid;
        float4 c = g_C4[gn];
        c.x *= step; c.y *= step; c.z *= step; c.w *= step;
        cnS[tid] = c;
        rinvS[tid] = g_rowinv[gn];
    }
    const int c = tid & 63;
    const int rg = tid >> 6;
    for (int j = chunk; j <= i; j += 8) {
        __syncthreads();
        if (tid < 64) cmS[tid] = g_C4[b * NN + j * 64 + tid];
        __syncthreads();
        float4 cm = cmS[c];
        float colsum = 0.0f;
        const float* cbase = g_compat + (size_t)(b * NN + i * 64) * NN + j * 64 + c;
        if (j < i) {
#pragma unroll 4
            for (int rr = 0; rr < 16; rr++) {
                int r = rg + 4 * rr;
                float4 cn = cnS[r];
                float coef = 1.0f + cn.x * cm.x + cn.y * cm.y + cn.z * cm.z + cn.w * cm.w;
                colsum += ex2_(cbase[(size_t)r * NN] * coef) * rinvS[r];
            }
        } else {
            for (int rr = 0; rr < 16; rr++) {
                int r = rg + 4 * rr;
                if (c <= r) {
                    float4 cn = cnS[r];
                    float coef = 1.0f + cn.x * cm.x + cn.y * cm.y + cn.z * cm.z + cn.w * cm.w;
                    colsum += ex2_(cbase[(size_t)r * NN] * coef) * rinvS[r];
                }
            }
        }
        colS[rg][c] = colsum;
        __syncthreads();
        if (tid < 64) {
            float v = colS[0][tid] + colS[1][tid] + colS[2][tid] + colS[3][tid];
            atomicAdd(g_received + b * NN + j * 64 + tid, v);
        }
    }
}

// ---------------- charge update ----------------
__global__ void charge_kernel(int p, const float* __restrict__ decay_p) {
    int idx = blockIdx.x * blockDim.x + threadIdx.x;
    if (idx >= BN) return;
    float decay = *decay_p;
    float r = g_received[idx];
    float* c4 = (float*)g_C4;
    float cprev = (p == 0) ? g_charge0[idx] : c4[idx * 4 + (p - 1)];
    c4[idx * 4 + p] = cprev * (1.0f - decay * sigmoidf_(r - 1.0f));
    g_received[idx] = 0.0f;
}

// ---------------- attn@V: 64x64 tiles, split-m chunks (R2 scalar) ----------------
__global__ __launch_bounds__(256) void attnv_kernel(const float* __restrict__ step_p) {
    const int i = blockIdx.x;
    const int b = blockIdx.y;
    const int chunk = blockIdx.z;
    if (chunk > i) return;
    const int n0 = i * 64;
    __shared__ float attnS[64][65];
    __shared__ float Vs[64][64];
    __shared__ float4 cnS[64];
    __shared__ float4 cmS[64];
    __shared__ float rinvS[64];
    const int tid = threadIdx.x;
    const float step = *step_p;
    if (tid < 64) {
        int gn = b * NN + n0 + tid;
        float4 cc = g_C4[gn];
        cc.x *= step; cc.y *= step; cc.z *= step; cc.w *= step;
        cnS[tid] = cc;
        rinvS[tid] = g_rowinv[gn];
    }
    float acc[4][4] = {{0.f}};
    const int tr = tid >> 4, tc = tid & 15;

    for (int j = chunk; j <= i; j += 4) {
        const int m0 = j * 64;
        __syncthreads();
        if (tid < 64) cmS[tid] = g_C4[b * NN + m0 + tid];
        {
            int m = tid >> 4;
            int d4 = (tid & 15) << 2;
#pragma unroll
            for (int it = 0; it < 4; it++) {
                int mm = m + it * 16;
                float4 v = *(const float4*)(g_V + (size_t)(b * NN + m0 + mm) * DK + d4);
                Vs[mm][d4 + 0] = v.x; Vs[mm][d4 + 1] = v.y;
                Vs[mm][d4 + 2] = v.z; Vs[mm][d4 + 3] = v.w;
            }
        }
        __syncthreads();
        for (int qq = tid; qq < 4096; qq += 256) {
            int r = qq >> 6, m = qq & 63;
            int n = n0 + r, mg = m0 + m;
            float v = 0.0f;
            if (mg <= n) {
                float4 cn = cnS[r], cm = cmS[m];
                float coef = 1.0f + cn.x * cm.x + cn.y * cm.y + cn.z * cm.z + cn.w * cm.w;
                v = ex2_(g_compat[(size_t)(b * NN + n) * NN + mg] * coef) * rinvS[r];
            }
            attnS[r][m] = v;
        }
        __syncthreads();
#pragma unroll 8
        for (int k = 0; k < 64; k++) {
            float ra[4], rb[4];
#pragma unroll
            for (int x = 0; x < 4; x++) ra[x] = attnS[tr * 4 + x][k];
#pragma unroll
            for (int y = 0; y < 4; y++) rb[y] = Vs[k][tc + 16 * y];
#pragma unroll
            for (int x = 0; x < 4; x++)
#pragma unroll
                for (int y = 0; y < 4; y++) acc[x][y] += ra[x] * rb[y];
        }
    }
#pragma unroll
    for (int x = 0; x < 4; x++) {
        float* dst = g_attV + (size_t)(b * NN + n0 + tr * 4 + x) * DK;
#pragma unroll
        for (int y = 0; y < 4; y++) atomicAdd(dst + tc + 16 * y, acc[x][y]);
    }
}

// ---------------- out = 0.1 * attV @ Wo^T (R2 scalar) ----------------
__global__ __launch_bounds__(256) void outgemm_kernel(const float* __restrict__ Wo,
                                                      float* __restrict__ out) {
    const int mi = blockIdx.x;
    const int ni = blockIdx.y;
    __shared__ float Ash[64][65];
    __shared__ float Bsh[64][64];
    const int tid = threadIdx.x;
    {
        int r = tid >> 4;
        int kk = (tid & 15) << 2;
#pragma unroll
        for (int it = 0; it < 4; it++) {
            int rr = r + it * 16;
            float4 v = *(const float4*)(g_attV + (size_t)(mi * 64 + rr) * DK + kk);
            Ash[kk + 0][rr] = v.x; Ash[kk + 1][rr] = v.y;
            Ash[kk + 2][rr] = v.z; Ash[kk + 3][rr] = v.w;
        }
        int jc = tid & 63;
        int ks0 = tid >> 6;
        const float* wb = Wo + (size_t)(ni * 64 + jc) * DK;
#pragma unroll
        for (int it = 0; it < 4; it++) {
            int k4 = (ks0 + it * 4) << 2;
            float4 v = *(const float4*)(wb + k4);
            Bsh[k4 + 0][jc] = v.x; Bsh[k4 + 1][jc] = v.y;
            Bsh[k4 + 2][jc] = v.z; Bsh[k4 + 3][jc] = v.w;
        }
    }
    __syncthreads();
    const int tr = tid >> 4, tc = tid & 15;
    float acc[4][4] = {{0.f}};
#pragma unroll
    for (int k = 0; k < 64; k++) {
        float ra[4], rb[4];
#pragma unroll
        for (int x = 0; x < 4; x++) ra[x] = Ash[k][tr * 4 + x];
#pragma unroll
        for (int y = 0; y < 4; y++) rb[y] = Bsh[k][tc + 16 * y];
#pragma unroll
        for (int x = 0; x < 4; x++)
#pragma unroll
            for (int y = 0; y < 4; y++) acc[x][y] += ra[x] * rb[y];
    }
#pragma unroll
    for (int x = 0; x < 4; x++) {
        size_t base = (size_t)(mi * 64 + tr * 4 + x) * DD + ni * 64;
#pragma unroll
        for (int y = 0; y < 4; y++) out[base + tc + 16 * y] = 0.1f * acc[x][y];
    }
}

// ---------------- launch ----------------
extern "C" void kernel_launch(void* const* d_in, const int* in_sizes, int n_in,
                              void* d_out, int out_size) {
    const float* hidden  = (const float*)d_in[0];
    const float* W1      = (const float*)d_in[1];
    const float* b1      = (const float*)d_in[2];
    const float* W2      = (const float*)d_in[3];
    const float* b2      = (const float*)d_in[4];
    const float* Wq      = (const float*)d_in[5];
    const float* Wk      = (const float*)d_in[6];
    const float* Wc      = (const float*)d_in[7];
    const float* bc      = (const float*)d_in[8];
    const float* Wv      = (const float*)d_in[9];
    const float* Wo      = (const float*)d_in[10];
    const float* step_p  = (const float*)d_in[11];
    const float* decay_p = (const float*)d_in[12];
    float* out = (float*)d_out;

    init_kernel<<<2048, 256>>>();
    wsplit_kernel<<<512, 256>>>(W1, Wv);
    gemm1_mma2_kernel<<<dim3(128, 2), 256>>>(hidden);
    reduce2_kernel<<<4096, 256>>>(b1);
    feat_kernel<<<BN / 8, 256>>>(W2, b2, Wq, Wk, Wc, bc);
    compat_kernel<<<dim3(528, BB), 256>>>();
    for (int p = 0; p < NSTEPS; p++) {
        rowsum_kernel<<<BN, 256>>>(step_p);
        colsum_kernel<<<dim3(NN / 64, BB, 8), 256>>>(step_p);
        charge_kernel<<<BN / 256, 256>>>(p, decay_p);
    }
    rowsum_kernel<<<BN, 256>>>(step_p);
    attnv_kernel<<<dim3(NN / 64, BB, 4), 256>>>(step_p);
    outgemm_kernel<<<dim3(BN / 64, DD / 64), 256>>>(Wo, out);
}